// round 14
// baseline (speedup 1.0000x reference)
#include <cuda_runtime.h>
#include <cuda_bf16.h>
#include <math.h>
#include <stdint.h>

#define N_ROWS 4096
#define DIM    1024
#define H1     512
#define H2     256
#define LAT    128
#define SLOPE  0.01f
#define NB     (N_ROWS / 128)
#define NBJ    (N_ROWS / 256)
#define NKC_X  (DIM / 64)
#define NKC_L  (LAT / 64)
#define TILE_ELEMS 8192
#define TILE_BYTES 16384
#define NBLK_DIST 272               /* sum over bi of (NBJ - bi/2) */

#if defined(__CUDA_ARCH_FEAT_SM103_ALL) || defined(__CUDA_ARCH_FEAT_SM100_ALL) || defined(__CUDA_ARCH_FEAT_SM101_ALL)
#define HAS_TCGEN05 1
#else
#define HAS_TCGEN05 0
#endif

// -------- scratch --------
__device__ float g_lat[N_ROWS * LAT];
__device__ float g_rx[N_ROWS];
__device__ float g_rl[N_ROWS];
__device__ double g_stats[5];
__device__ __align__(16) float g_dx[NBLK_DIST * 32768];   // fp32: exact roundtrip
__device__ __align__(16) __nv_bfloat16 g_xh[NB * NKC_X * TILE_ELEMS];
__device__ __align__(16) __nv_bfloat16 g_xl[NB * NKC_X * TILE_ELEMS];
__device__ __align__(16) __nv_bfloat16 g_lh[NB * NKC_L * TILE_ELEMS];
__device__ __align__(16) __nv_bfloat16 g_ll[NB * NKC_L * TILE_ELEMS];
__device__ __align__(16) __nv_bfloat16 g_a1h[N_ROWS * H1], g_a1l[N_ROWS * H1];
__device__ __align__(16) __nv_bfloat16 g_a2h[N_ROWS * H2], g_a2l[N_ROWS * H2];
__device__ __align__(16) __nv_bfloat16 g_a4h[N_ROWS * H2], g_a4l[N_ROWS * H2];
__device__ __align__(16) __nv_bfloat16 g_a5h[N_ROWS * H1], g_a5l[N_ROWS * H1];
__device__ __align__(16) __nv_bfloat16 g_we1h[H1 * DIM], g_we1l[H1 * DIM];
__device__ __align__(16) __nv_bfloat16 g_we2h[H2 * H1],  g_we2l[H2 * H1];
__device__ __align__(16) __nv_bfloat16 g_we3h[LAT * H2], g_we3l[LAT * H2];
__device__ __align__(16) __nv_bfloat16 g_wd1h[H2 * LAT], g_wd1l[H2 * LAT];
__device__ __align__(16) __nv_bfloat16 g_wd2h[H1 * H2],  g_wd2l[H1 * H2];
__device__ __align__(16) __nv_bfloat16 g_wd3h[DIM * H1], g_wd3l[DIM * H1];

__global__ void zero_stats_kernel() {
    if (threadIdx.x < 5) g_stats[threadIdx.x] = 0.0;
}

// ================= PTX helpers =================
__device__ __forceinline__ uint32_t smem_u32(const void* p) {
    uint32_t a;
    asm("{ .reg .u64 t; cvta.to.shared.u64 t, %1; cvt.u32.u64 %0, t; }" : "=r"(a) : "l"(p));
    return a;
}
__device__ __forceinline__ uint32_t elect_one() {
    uint32_t p;
    asm volatile("{\n\t.reg .pred p;\n\telect.sync _|p, 0xFFFFFFFF;\n\tselp.b32 %0, 1, 0, p;\n\t}" : "=r"(p));
    return p;
}
#define MBAR_INIT(mbar, c) \
    asm volatile("mbarrier.init.shared.b64 [%0], %1;" :: "r"(mbar), "r"((uint32_t)(c)) : "memory")
#define MBAR_INVAL(mbar) \
    asm volatile("mbarrier.inval.shared.b64 [%0];" :: "r"(mbar) : "memory")
#define MBAR_ARRIVE(mbar) \
    asm volatile("mbarrier.arrive.shared.b64 _, [%0];" :: "r"(mbar) : "memory")
#define MBAR_EXPECT_TX(mbar, bytes) \
    asm volatile("mbarrier.arrive.expect_tx.shared.b64 _, [%0], %1;" \
                 :: "r"(mbar), "r"((uint32_t)(bytes)) : "memory")

__device__ __forceinline__ void mbar_wait_parity(uint32_t mbar, uint32_t parity) {
    uint32_t done;
    asm volatile("{\n\t.reg .pred p;\n\t"
                 "mbarrier.try_wait.parity.acquire.cta.shared::cta.b64 p, [%1], %2;\n\t"
                 "selp.b32 %0, 1, 0, p;\n\t}" : "=r"(done) : "r"(mbar), "r"(parity) : "memory");
    if (!done) {
        asm volatile("{\n\t.reg .pred P1;\n\t"
                     "WL_%=:\n\t"
                     "mbarrier.try_wait.parity.acquire.cta.shared::cta.b64 P1, [%0], %1, 0x989680;\n\t"
                     "@P1 bra.uni WD_%=;\n\t"
                     "bra.uni WL_%=;\n\t"
                     "WD_%=:\n\t}" :: "r"(mbar), "r"(parity) : "memory");
    }
}

#if HAS_TCGEN05
#define TC_ALLOC(smem_addr, n) \
    asm volatile("tcgen05.alloc.cta_group::1.sync.aligned.shared::cta.b32 [%0], %1;" \
                 :: "r"(smem_addr), "r"((uint32_t)(n)) : "memory")
#define TC_DEALLOC(tmem, n) \
    asm volatile("tcgen05.dealloc.cta_group::1.sync.aligned.b32 %0, %1;" :: "r"(tmem), "r"((uint32_t)(n)))
#define TC_COMMIT(mbar) \
    asm volatile("tcgen05.commit.cta_group::1.mbarrier::arrive::one.shared::cluster.b64 [%0];" \
                 :: "r"(mbar) : "memory")
#define TC_FENCE_AFTER()  asm volatile("tcgen05.fence::after_thread_sync;" ::: "memory")
#define TC_WAIT_LD()      asm volatile("tcgen05.wait::ld.sync.aligned;" ::: "memory")
#define BULK_G2S(dst, src, bytes, mbar) \
    asm volatile("cp.async.bulk.shared::cta.global.mbarrier::complete_tx::bytes [%0], [%1], %2, [%3];" \
                 :: "r"(dst), "l"(src), "r"((uint32_t)(bytes)), "r"(mbar) : "memory")

__device__ __forceinline__ void mma_f16_ss(uint32_t d_tmem, uint64_t a_desc, uint64_t b_desc,
                                           uint32_t idesc, bool accum) {
    uint32_t en = accum ? 1u : 0u;
    asm volatile("{\n\t.reg .pred p;\n\t"
                 "setp.ne.u32 p, %5, 0;\n\t"
                 "tcgen05.mma.cta_group::1.kind::f16 [%0], %1, %2, %3, {%4, %4, %4, %4}, p;\n\t}"
                 :: "r"(d_tmem), "l"(a_desc), "l"(b_desc), "r"(idesc), "r"(0u), "r"(en)
                 : "memory");
}

#define LDTM32(r, addr) \
    asm volatile("tcgen05.ld.sync.aligned.32x32b.x32.b32 " \
        "{%0, %1, %2, %3, %4, %5, %6, %7, %8, %9, %10, %11, %12, %13, %14, %15, " \
        " %16, %17, %18, %19, %20, %21, %22, %23, %24, %25, %26, %27, %28, %29, %30, %31}, [%32];" \
        : "=r"((r)[0]), "=r"((r)[1]), "=r"((r)[2]), "=r"((r)[3]), \
          "=r"((r)[4]), "=r"((r)[5]), "=r"((r)[6]), "=r"((r)[7]), \
          "=r"((r)[8]), "=r"((r)[9]), "=r"((r)[10]), "=r"((r)[11]), \
          "=r"((r)[12]), "=r"((r)[13]), "=r"((r)[14]), "=r"((r)[15]), \
          "=r"((r)[16]), "=r"((r)[17]), "=r"((r)[18]), "=r"((r)[19]), \
          "=r"((r)[20]), "=r"((r)[21]), "=r"((r)[22]), "=r"((r)[23]), \
          "=r"((r)[24]), "=r"((r)[25]), "=r"((r)[26]), "=r"((r)[27]), \
          "=r"((r)[28]), "=r"((r)[29]), "=r"((r)[30]), "=r"((r)[31]) \
        : "r"(addr))

static __device__ __forceinline__ uint64_t make_desc(uint32_t addr) {
    const uint64_t base = (uint64_t(2) << 61) | (uint64_t(1) << 46)
                        | (uint64_t(64) << 32) | (uint64_t(1) << 16);
    return base | ((uint64_t)(addr >> 4) & 0x3FFF);
}
#define IDESC_N128 0x8200490u
#define IDESC_N256 0x8400490u
#endif // HAS_TCGEN05

// ================= row squared-norms =================
__global__ void rownorm_kernel(const float* __restrict__ X, float* __restrict__ r, int K) {
    int row = blockIdx.x;
    const float* p = X + (size_t)row * K;
    float s = 0.f;
    for (int k = threadIdx.x; k < K; k += blockDim.x) {
        float v = p[k];
        s += v * v;
    }
#pragma unroll
    for (int off = 16; off > 0; off >>= 1)
        s += __shfl_down_sync(0xffffffffu, s, off);
    __shared__ float sm[32];
    int lane = threadIdx.x & 31, wid = threadIdx.x >> 5;
    if (lane == 0) sm[wid] = s;
    __syncthreads();
    if (wid == 0) {
        int nw = blockDim.x >> 5;
        float v = (lane < nw) ? sm[lane] : 0.f;
#pragma unroll
        for (int off = 16; off > 0; off >>= 1)
            v += __shfl_down_sync(0xffffffffu, v, off);
        if (lane == 0) r[row] = v;
    }
}

// ================= fused split-convert =================
struct alignas(16) bf16x8 { __nv_bfloat16 v[8]; };
struct CvtSeg { const float* src; __nv_bfloat16* dh; __nv_bfloat16* dl; int K; unsigned base; };
struct CvtArgs { CvtSeg seg[7]; unsigned total; };

__global__ void convert_all_kernel(CvtArgs args) {
    unsigned gid = blockIdx.x * blockDim.x + threadIdx.x;
    if (gid >= args.total) return;
    int si = 0;
#pragma unroll
    for (int i = 1; i < 7; i++)
        if (gid >= args.seg[i].base) si = i;
    const CvtSeg s = args.seg[si];
    unsigned idx = gid - s.base;
    int K = s.K, gpr = K >> 3, nkc = K >> 6;
    int r  = idx / gpr;
    int k0 = (idx - r * gpr) * 8;

    const float* p = s.src + (size_t)r * K + k0;
    float4 v0 = *(const float4*)p;
    float4 v1 = *(const float4*)(p + 4);
    float f[8] = {v0.x, v0.y, v0.z, v0.w, v1.x, v1.y, v1.z, v1.w};

    bf16x8 ph, pl;
#pragma unroll
    for (int m = 0; m < 8; m++) {
        __nv_bfloat16 h = __float2bfloat16(f[m]);
        ph.v[m] = h;
        pl.v[m] = __float2bfloat16(f[m] - __bfloat162float(h));
    }

    int rb = r >> 7, lr = r & 127;
    int kc = k0 >> 6, g = (k0 & 63) >> 3;
    int gsw = g ^ (lr & 7);
    size_t off = (((size_t)rb * nkc + kc) * 128 + lr) * 64 + gsw * 8;
    *(bf16x8*)&s.dh[off] = ph;
    *(bf16x8*)&s.dl[off] = pl;
}

// ================= tcgen05 GEMM + bias + LeakyReLU (R9 config) =================
#define GS 3
__global__ void __launch_bounds__(256, 1)
tc_gemm_bias_lrelu(const __nv_bfloat16* __restrict__ ah, const __nv_bfloat16* __restrict__ al,
                   const __nv_bfloat16* __restrict__ wh, const __nv_bfloat16* __restrict__ wl,
                   const float* __restrict__ bias,
                   float* __restrict__ Cfp,
                   __nv_bfloat16* __restrict__ oh, __nv_bfloat16* __restrict__ ol,
                   int N, int NC, int write_fp32, int write_split) {
    const int nb = blockIdx.x, mb = blockIdx.y;
    const int n0 = nb * 128, m0 = mb * 128;
    const int t = threadIdx.x;

#if HAS_TCGEN05
    extern __shared__ char dsm_raw[];
    char* dsm = (char*)(((uintptr_t)dsm_raw + 1023) & ~(uintptr_t)1023);
    __shared__ __align__(8) unsigned long long s_mbar[2 * GS + 1];
    __shared__ uint32_t s_tmem;

    const int wid = t >> 5;
    const int lid = t & 31;
    const uint32_t mb0   = smem_u32(&s_mbar[0]);
    const uint32_t donem = mb0 + 2 * GS * 8;
#define FULLB(b)  (mb0 + (uint32_t)(b) * 8)
#define EMPTYB(b) (mb0 + (uint32_t)(GS + (b)) * 8)

    if (wid == 0) TC_ALLOC(smem_u32(&s_tmem), 128);
    if (t == 0) {
        for (int k = 0; k < 2 * GS; k++) MBAR_INIT(mb0 + k * 8, 1);
        MBAR_INIT(donem, 1);
    }
    __syncthreads();
    const uint32_t D = s_tmem;
    const uint32_t smem_base = smem_u32(dsm);

    if (wid == 0 && elect_one()) {
        const int np = (NC < GS) ? NC : GS;
        for (int k = 0; k < np; k++) {
            const uint32_t bufb = smem_base + (uint32_t)k * 65536;
            MBAR_EXPECT_TX(FULLB(k), 65536);
            BULK_G2S(bufb,         (const char*)(ah + ((size_t)mb * NC + k) * TILE_ELEMS), TILE_BYTES, FULLB(k));
            BULK_G2S(bufb + 16384, (const char*)(al + ((size_t)mb * NC + k) * TILE_ELEMS), TILE_BYTES, FULLB(k));
            BULK_G2S(bufb + 32768, (const char*)(wh + ((size_t)nb * NC + k) * TILE_ELEMS), TILE_BYTES, FULLB(k));
            BULK_G2S(bufb + 49152, (const char*)(wl + ((size_t)nb * NC + k) * TILE_ELEMS), TILE_BYTES, FULLB(k));
        }
#pragma unroll 1
        for (int n = 0; n < NC; n++) {
            const int b = n % GS, q = n / GS;
            const uint32_t bufb = smem_base + (uint32_t)b * 65536;
            mbar_wait_parity(FULLB(b), (uint32_t)(q & 1));

            uint64_t dAh = make_desc(bufb);
            uint64_t dAl = make_desc(bufb + 16384);
            uint64_t dWh = make_desc(bufb + 32768);
            uint64_t dWl = make_desc(bufb + 49152);
#pragma unroll
            for (int s = 0; s < 4; s++) {
                uint64_t off = s * 2;
                mma_f16_ss(D, dAh + off, dWh + off, IDESC_N128, !(n == 0 && s == 0));
                mma_f16_ss(D, dAh + off, dWl + off, IDESC_N128, true);
                mma_f16_ss(D, dAl + off, dWh + off, IDESC_N128, true);
            }
            TC_COMMIT(EMPTYB(b));

            if (n + GS < NC) {
                const int m = n + GS;
                mbar_wait_parity(EMPTYB(b), (uint32_t)(q & 1));
                MBAR_EXPECT_TX(FULLB(b), 65536);
                BULK_G2S(bufb,         (const char*)(ah + ((size_t)mb * NC + m) * TILE_ELEMS), TILE_BYTES, FULLB(b));
                BULK_G2S(bufb + 16384, (const char*)(al + ((size_t)mb * NC + m) * TILE_ELEMS), TILE_BYTES, FULLB(b));
                BULK_G2S(bufb + 32768, (const char*)(wh + ((size_t)nb * NC + m) * TILE_ELEMS), TILE_BYTES, FULLB(b));
                BULK_G2S(bufb + 49152, (const char*)(wl + ((size_t)nb * NC + m) * TILE_ELEMS), TILE_BYTES, FULLB(b));
            }
        }
        for (int n = (NC > GS ? NC - GS : 0); n < NC; n++)
            mbar_wait_parity(EMPTYB(n % GS), (uint32_t)((n / GS) & 1));
        MBAR_ARRIVE(donem);
    }
    mbar_wait_parity(donem, 0u);
    TC_FENCE_AFTER();

    const int wg  = wid >> 2;
    const int sub = wid & 3;
    const int lr  = sub * 32 + lid;
    const int m   = m0 + lr;
    const int nkc_out = N >> 6;

#pragma unroll
    for (int bb = 0; bb < 2; bb++) {
        const int colbase = wg * 64 + bb * 32;
        uint32_t dr[32];
        LDTM32(dr, D + colbase);
        TC_WAIT_LD();
        float v[32];
#pragma unroll
        for (int c = 0; c < 32; c++) {
            float x = __uint_as_float(dr[c]) + __ldg(&bias[n0 + colbase + c]);
            v[c] = (x >= 0.f) ? x : SLOPE * x;
        }
        if (write_fp32) {
#pragma unroll
            for (int c = 0; c < 32; c++)
                Cfp[(size_t)m * N + n0 + colbase + c] = v[c];
        }
        if (write_split) {
#pragma unroll
            for (int g8 = 0; g8 < 4; g8++) {
                int nn = n0 + colbase + g8 * 8;
                int kc = nn >> 6, g = (nn & 63) >> 3;
                int gsw = g ^ (lr & 7);
                size_t off = (((size_t)mb * nkc_out + kc) * 128 + lr) * 64 + gsw * 8;
                bf16x8 ph, pl;
#pragma unroll
                for (int e = 0; e < 8; e++) {
                    float x = v[g8 * 8 + e];
                    __nv_bfloat16 h = __float2bfloat16(x);
                    ph.v[e] = h;
                    pl.v[e] = __float2bfloat16(x - __bfloat162float(h));
                }
                *(bf16x8*)&oh[off] = ph;
                *(bf16x8*)&ol[off] = pl;
            }
        }
    }

    __syncthreads();
    if (t == 0) {
        for (int k = 0; k < 2 * GS; k++) MBAR_INVAL(mb0 + k * 8);
        MBAR_INVAL(donem);
    }
    __syncthreads();
    if (wid == 0) TC_DEALLOC(D, 128);
#undef FULLB
#undef EMPTYB

#else
    const int K = NC * 64;
    const int lr0 = t & 127;
    const int m = m0 + lr0;
    const int jh = (t >> 7) * 64;
    const int nkc_out = N >> 6;
    for (int jj = 0; jj < 64; jj++) {
        int nn = n0 + jh + jj;
        int wrb = nn >> 7, wlr = nn & 127;
        float acc = 0.f;
        for (int k = 0; k < K; k++) {
            int kc = k >> 6, g = (k & 63) >> 3, e = k & 7;
            size_t aoff = (((size_t)mb * NC + kc) * 128 + lr0) * 64 + (size_t)((g ^ (lr0 & 7)) * 8 + e);
            size_t woff = (((size_t)wrb * NC + kc) * 128 + wlr) * 64 + (size_t)((g ^ (wlr & 7)) * 8 + e);
            float av = __bfloat162float(ah[aoff]) + __bfloat162float(al[aoff]);
            float wv = __bfloat162float(wh[woff]) + __bfloat162float(wl[woff]);
            acc += av * wv;
        }
        float x = acc + bias[nn];
        x = (x >= 0.f) ? x : SLOPE * x;
        if (write_fp32) Cfp[(size_t)m * N + nn] = x;
        if (write_split) {
            __nv_bfloat16 h = __float2bfloat16(x);
            int kc = nn >> 6, g = (nn & 63) >> 3;
            size_t off = (((size_t)mb * nkc_out + kc) * 128 + lr0) * 64 + (size_t)((g ^ (lr0 & 7)) * 8 + (nn & 7));
            oh[off] = h;
            ol[off] = __float2bfloat16(x - __bfloat162float(h));
        }
    }
#endif
}

// ================= shared helpers for split dist kernels =================
__device__ __forceinline__ void dist_block_decode(int b, int& bi, int& jb2) {
    bi = 0;
    int rem = b;
    while (rem >= NBJ - (bi >> 1)) { rem -= NBJ - (bi >> 1); bi++; }
    jb2 = (bi >> 1) + rem;
}

__device__ __forceinline__ void stats_reduce(double* red, int t, const float* vals,
                                             const int* which, int nv) {
    for (int v = 0; v < nv; v++) {
        red[t] = (double)vals[v];
        __syncthreads();
        for (int off = 128; off > 0; off >>= 1) {
            if (t < off) red[t] += red[t + off];
            __syncthreads();
        }
        if (t == 0) atomicAdd(&g_stats[which[v]], red[0]);
        __syncthreads();
    }
}

#if HAS_TCGEN05
template <int DSN>
__device__ __forceinline__ void gram_pipeline(
        const __nv_bfloat16* base_arr, int nkc, int nch,
        int bi, int jb2, uint32_t D, uint32_t smem_base,
        uint32_t mb0, uint32_t donem, int wid) {
#define FULLB(b)  (mb0 + (uint32_t)(b) * 8)
#define EMPTYB(b) (mb0 + (uint32_t)(DSN + (b)) * 8)
    if (wid == 0 && elect_one()) {
        auto docopy = [&](int n, int bsel) {
            const uint32_t bufb = smem_base + (uint32_t)bsel * 49152;
            const uint32_t fb = FULLB(bsel);
            MBAR_EXPECT_TX(fb, 49152);
            BULK_G2S(bufb, (const char*)(base_arr + ((size_t)bi * nkc + n) * TILE_ELEMS), TILE_BYTES, fb);
            BULK_G2S(bufb + 16384, (const char*)(base_arr + ((size_t)(jb2 * 2) * nkc + n) * TILE_ELEMS), TILE_BYTES, fb);
            BULK_G2S(bufb + 32768, (const char*)(base_arr + ((size_t)(jb2 * 2 + 1) * nkc + n) * TILE_ELEMS), TILE_BYTES, fb);
        };
        const int np = (nch < DSN) ? nch : DSN;
        for (int k = 0; k < np; k++) docopy(k, k);
#pragma unroll 1
        for (int n = 0; n < nch; n++) {
            const int bsel = n % DSN, q = n / DSN;
            const uint32_t bufb = smem_base + (uint32_t)bsel * 49152;
            mbar_wait_parity(FULLB(bsel), (uint32_t)(q & 1));
            uint64_t dA = make_desc(bufb), dB = make_desc(bufb + 16384);
#pragma unroll
            for (int s = 0; s < 4; s++)
                mma_f16_ss(D, dA + s * 2, dB + s * 2, IDESC_N256, !(n == 0 && s == 0));
            TC_COMMIT(EMPTYB(bsel));
            if (n + DSN < nch) {
                mbar_wait_parity(EMPTYB(bsel), (uint32_t)(q & 1));
                docopy(n + DSN, bsel);
            }
        }
        for (int n = (nch > DSN ? nch - DSN : 0); n < nch; n++)
            mbar_wait_parity(EMPTYB(n % DSN), (uint32_t)((n / DSN) & 1));
        MBAR_ARRIVE(donem);
    }
    mbar_wait_parity(donem, 0u);
    TC_FENCE_AFTER();
#undef FULLB
#undef EMPTYB
}
#endif

// ================= dist part 1: x Gram -> dx (fp32 gmem) + Sdx, Sdx2 =================
#define DS 4
__global__ void __launch_bounds__(256, 1)
dist_x_kernel(const __nv_bfloat16* __restrict__ xh,
              const float* __restrict__ rx,
              float* __restrict__ dxout) {
    int bi, jb2;
    dist_block_decode(blockIdx.x, bi, jb2);
    const bool dcheck = (jb2 == (bi >> 1));
    const int i0 = bi * 128, j0 = jb2 * 256;

    __shared__ double red[256];
    const int t = threadIdx.x;
    float fs1 = 0.f, fs11 = 0.f;

#if HAS_TCGEN05
    extern __shared__ char dsm_raw[];
    char* dsm = (char*)(((uintptr_t)dsm_raw + 1023) & ~(uintptr_t)1023);
    __shared__ __align__(8) unsigned long long s_mbar[2 * DS + 1];
    __shared__ uint32_t s_tmem;

    const int wid = t >> 5;
    const int lid = t & 31;
    const uint32_t mb0   = smem_u32(&s_mbar[0]);
    const uint32_t donem = mb0 + 2 * DS * 8;

    if (wid == 0) TC_ALLOC(smem_u32(&s_tmem), 256);
    if (t == 0) {
        for (int k = 0; k < 2 * DS; k++) MBAR_INIT(mb0 + k * 8, 1);
        MBAR_INIT(donem, 1);
    }
    __syncthreads();
    const uint32_t D_X = s_tmem;

    gram_pipeline<DS>(xh, NKC_X, NKC_X, bi, jb2, D_X, smem_u32(dsm), mb0, donem, wid);

    const int wg  = wid >> 2;
    const int sub = wid & 3;
    const int i = i0 + sub * 32 + lid;
    const float rxi = __ldg(&rx[i]);

#pragma unroll 1
    for (int bb = 0; bb < 4; bb++) {
        const int colbase = wg * 128 + bb * 32;
        uint32_t xg[32];
        LDTM32(xg, D_X + colbase);
        TC_WAIT_LD();
        float dxv[32];
#pragma unroll
        for (int c = 0; c < 32; c++) {
            int j = j0 + colbase + c;
            float dx = 0.f;
            if (!dcheck || j > i) {
                float sqx = rxi + __ldg(&rx[j]) - 2.f * __uint_as_float(xg[c]);
                dx = sqrtf(fmaxf(sqx, 0.f));
                fs1  += dx;
                fs11 += dx * dx;
            }
            dxv[c] = dx;
        }
        size_t off = ((size_t)blockIdx.x * 1024 + (size_t)bb * 256 + t) * 32;
#pragma unroll
        for (int q = 0; q < 8; q++)
            *(float4*)&dxout[off + q * 4] = *(const float4*)&dxv[q * 4];
    }

    __syncthreads();
    if (t == 0) {
        for (int k = 0; k < 2 * DS; k++) MBAR_INVAL(mb0 + k * 8);
        MBAR_INVAL(donem);
    }
    __syncthreads();
    if (wid == 0) TC_DEALLOC(D_X, 256);

#else  // fallback
    const int wg  = (t >> 5) >> 2;
    const int sub = (t >> 5) & 3;
    const int lid = t & 31;
    const int i = i0 + sub * 32 + lid;
    int ib = i >> 7, ilr = i & 127;
    float rxi = rx[i];
    for (int bb = 0; bb < 4; bb++) {
        const int colbase = wg * 128 + bb * 32;
        size_t off = ((size_t)blockIdx.x * 1024 + (size_t)bb * 256 + t) * 32;
        for (int c = 0; c < 32; c++) {
            int j = j0 + colbase + c;
            float dx = 0.f;
            if (!dcheck || j > i) {
                int jb = j >> 7, jlr = j & 127;
                float gx = 0.f;
                for (int k = 0; k < DIM; k++) {
                    int kc = k >> 6, g = (k & 63) >> 3, e = k & 7;
                    size_t ioff = (((size_t)ib * NKC_X + kc) * 128 + ilr) * 64 + (size_t)((g ^ (ilr & 7)) * 8 + e);
                    size_t joff = (((size_t)jb * NKC_X + kc) * 128 + jlr) * 64 + (size_t)((g ^ (jlr & 7)) * 8 + e);
                    gx += __bfloat162float(xh[ioff]) * __bfloat162float(xh[joff]);
                }
                dx = sqrtf(fmaxf(rxi + rx[j] - 2.f * gx, 0.f));
                fs1 += dx;
                fs11 += dx * dx;
            }
            dxout[off + c] = dx;
        }
    }
#endif

    float vals[2] = {fs1, fs11};
    const int which[2] = {0, 2};
    stats_reduce(red, t, vals, which, 2);
}

// ================= dist part 2: latent Gram + dx reload -> Sdv, Sdv2, Sdxdv =======
__global__ void __launch_bounds__(256, 1)
dist_lat_kernel(const __nv_bfloat16* __restrict__ lh,
                const float* __restrict__ rl,
                const float* __restrict__ dxin) {
    int bi, jb2;
    dist_block_decode(blockIdx.x, bi, jb2);
    const bool dcheck = (jb2 == (bi >> 1));
    const int i0 = bi * 128, j0 = jb2 * 256;

    __shared__ double red[256];
    const int t = threadIdx.x;
    float fs2 = 0.f, fs22 = 0.f, fs12 = 0.f;

#if HAS_TCGEN05
    extern __shared__ char dsm_raw[];
    char* dsm = (char*)(((uintptr_t)dsm_raw + 1023) & ~(uintptr_t)1023);
    __shared__ __align__(8) unsigned long long s_mbar[2 * DS + 1];
    __shared__ uint32_t s_tmem;

    const int wid = t >> 5;
    const int lid = t & 31;
    const uint32_t mb0   = smem_u32(&s_mbar[0]);
    const uint32_t donem = mb0 + 2 * DS * 8;

    if (wid == 0) TC_ALLOC(smem_u32(&s_tmem), 256);
    if (t == 0) {
        for (int k = 0; k < 2 * DS; k++) MBAR_INIT(mb0 + k * 8, 1);
        MBAR_INIT(donem, 1);
    }
    __syncthreads();
    const uint32_t D_L = s_tmem;

    gram_pipeline<DS>(lh, NKC_L, NKC_L, bi, jb2, D_L, smem_u32(dsm), mb0, donem, wid);

    const int wg  = wid >> 2;
    const int sub = wid & 3;
    const int i = i0 + sub * 32 + lid;
    const float rli = __ldg(&rl[i]);

#pragma unroll 1
    for (int bb = 0; bb < 4; bb++) {
        const int colbase = wg * 128 + bb * 32;
        uint32_t lg[32];
        LDTM32(lg, D_L + colbase);
        TC_WAIT_LD();
        size_t off = ((size_t)blockIdx.x * 1024 + (size_t)bb * 256 + t) * 32;
        float dxv[32];
#pragma unroll
        for (int q = 0; q < 8; q++)
            *(float4*)&dxv[q * 4] = *(const float4*)&dxin[off + q * 4];
#pragma unroll
        for (int c = 0; c < 32; c++) {
            int j = j0 + colbase + c;
            if (!dcheck || j > i) {
                float sql = rli + __ldg(&rl[j]) - 2.f * __uint_as_float(lg[c]);
                float dv = sqrtf(fmaxf(sql, 0.f));
                float dx = dxv[c];
                fs2  += dv;
                fs22 += dv * dv;
                fs12 += dx * dv;
            }
        }
    }

    __syncthreads();
    if (t == 0) {
        for (int k = 0; k < 2 * DS; k++) MBAR_INVAL(mb0 + k * 8);
        MBAR_INVAL(donem);
    }
    __syncthreads();
    if (wid == 0) TC_DEALLOC(D_L, 256);

#else  // fallback
    const int wg  = (t >> 5) >> 2;
    const int sub = (t >> 5) & 3;
    const int lid = t & 31;
    const int i = i0 + sub * 32 + lid;
    int ib = i >> 7, ilr = i & 127;
    float rli = rl[i];
    for (int bb = 0; bb < 4; bb++) {
        const int colbase = wg * 128 + bb * 32;
        size_t off = ((size_t)blockIdx.x * 1024 + (size_t)bb * 256 + t) * 32;
        for (int c = 0; c < 32; c++) {
            int j = j0 + colbase + c;
            if (dcheck && j <= i) continue;
            int jb = j >> 7, jlr = j & 127;
            float gl = 0.f;
            for (int k = 0; k < LAT; k++) {
                int kc = k >> 6, g = (k & 63) >> 3, e = k & 7;
                size_t ioff = (((size_t)ib * NKC_L + kc) * 128 + ilr) * 64 + (size_t)((g ^ (ilr & 7)) * 8 + e);
                size_t joff = (((size_t)jb * NKC_L + kc) * 128 + jlr) * 64 + (size_t)((g ^ (jlr & 7)) * 8 + e);
                gl += __bfloat162float(lh[ioff]) * __bfloat162float(lh[joff]);
            }
            float dv = sqrtf(fmaxf(rli + rl[j] - 2.f * gl, 0.f));
            float dx = dxin[off + c];
            fs2 += dv; fs22 += dv * dv; fs12 += dx * dv;
        }
    }
#endif

    float vals[3] = {fs2, fs22, fs12};
    const int which[3] = {1, 3, 4};
    stats_reduce(red, t, vals, which, 3);
}

__global__ void finalize_kernel(float* __restrict__ out, long long idx) {
    const double n = (double)N_ROWS * (double)N_ROWS;
    double s1  = 2.0 * g_stats[0];
    double s2  = 2.0 * g_stats[1];
    double s11 = 2.0 * g_stats[2];
    double s22 = 2.0 * g_stats[3];
    double s12 = 2.0 * g_stats[4];
    double m1 = s1 / n;
    double m2 = s2 / n;
    double v1 = (s11 - n * m1 * m1) / (n - 1.0);
    double v2 = (s22 - n * m2 * m2) / (n - 1.0);
    double cov = s12 / n - m1 * m2;
    out[idx] = (float)(cov / sqrt(v1 * v2));
}

extern "C" void kernel_launch(void* const* d_in, const int* in_sizes, int n_in,
                              void* d_out, int out_size) {
    const float* x   = (const float*)d_in[0];
    const float* We1 = (const float*)d_in[1];
    const float* be1 = (const float*)d_in[2];
    const float* We2 = (const float*)d_in[3];
    const float* be2 = (const float*)d_in[4];
    const float* We3 = (const float*)d_in[5];
    const float* be3 = (const float*)d_in[6];
    const float* Wd1 = (const float*)d_in[7];
    const float* bd1 = (const float*)d_in[8];
    const float* Wd2 = (const float*)d_in[9];
    const float* bd2 = (const float*)d_in[10];
    const float* Wd3 = (const float*)d_in[11];
    const float* bd3 = (const float*)d_in[12];
    float* out = (float*)d_out;

    float* lat = nullptr; cudaGetSymbolAddress((void**)&lat, g_lat);
    float* rx  = nullptr; cudaGetSymbolAddress((void**)&rx,  g_rx);
    float* rl  = nullptr; cudaGetSymbolAddress((void**)&rl,  g_rl);
    float* dx  = nullptr; cudaGetSymbolAddress((void**)&dx,  g_dx);
#define SYM(T, v, s) T* v = nullptr; cudaGetSymbolAddress((void**)&v, s)
    SYM(__nv_bfloat16, xh, g_xh);   SYM(__nv_bfloat16, xl, g_xl);
    SYM(__nv_bfloat16, lh, g_lh);   SYM(__nv_bfloat16, ll, g_ll);
    SYM(__nv_bfloat16, a1h, g_a1h); SYM(__nv_bfloat16, a1l, g_a1l);
    SYM(__nv_bfloat16, a2h, g_a2h); SYM(__nv_bfloat16, a2l, g_a2l);
    SYM(__nv_bfloat16, a4h, g_a4h); SYM(__nv_bfloat16, a4l, g_a4l);
    SYM(__nv_bfloat16, a5h, g_a5h); SYM(__nv_bfloat16, a5l, g_a5l);
    SYM(__nv_bfloat16, we1h, g_we1h); SYM(__nv_bfloat16, we1l, g_we1l);
    SYM(__nv_bfloat16, we2h, g_we2h); SYM(__nv_bfloat16, we2l, g_we2l);
    SYM(__nv_bfloat16, we3h, g_we3h); SYM(__nv_bfloat16, we3l, g_we3l);
    SYM(__nv_bfloat16, wd1h, g_wd1h); SYM(__nv_bfloat16, wd1l, g_wd1l);
    SYM(__nv_bfloat16, wd2h, g_wd2h); SYM(__nv_bfloat16, wd2l, g_wd2l);
    SYM(__nv_bfloat16, wd3h, g_wd3h); SYM(__nv_bfloat16, wd3l, g_wd3l);
#undef SYM

    static cudaStream_t s2 = nullptr;
    static cudaEvent_t ev_cvt = nullptr, ev_lat = nullptr, ev_join = nullptr;
    if (s2 == nullptr) {
        cudaStreamCreateWithFlags(&s2, cudaStreamNonBlocking);
        cudaEventCreateWithFlags(&ev_cvt, cudaEventDisableTiming);
        cudaEventCreateWithFlags(&ev_lat, cudaEventDisableTiming);
        cudaEventCreateWithFlags(&ev_join, cudaEventDisableTiming);
    }

    zero_stats_kernel<<<1, 32>>>();
    {
        CvtArgs a;
        unsigned base = 0;
        auto set = [&](int i, const float* src, __nv_bfloat16* dh, __nv_bfloat16* dl,
                       int rows, int K) {
            a.seg[i] = {src, dh, dl, K, base};
            base += (unsigned)(rows * K / 8);
        };
        set(0, x,   xh,   xl,   N_ROWS, DIM);
        set(1, We1, we1h, we1l, H1,  DIM);
        set(2, We2, we2h, we2l, H2,  H1);
        set(3, We3, we3h, we3l, LAT, H2);
        set(4, Wd1, wd1h, wd1l, H2,  LAT);
        set(5, Wd2, wd2h, wd2l, H1,  H2);
        set(6, Wd3, wd3h, wd3l, DIM, H1);
        a.total = base;
        convert_all_kernel<<<(base + 255) / 256, 256>>>(a);
    }

    const int smem_gemm = GS * 65536 + 1024;
    const int smem_dist = DS * 49152 + 1024;
    cudaFuncSetAttribute(tc_gemm_bias_lrelu, cudaFuncAttributeMaxDynamicSharedMemorySize, smem_gemm);
    cudaFuncSetAttribute(dist_x_kernel, cudaFuncAttributeMaxDynamicSharedMemorySize, smem_dist);
    cudaFuncSetAttribute(dist_lat_kernel, cudaFuncAttributeMaxDynamicSharedMemorySize, smem_dist);

    // fork after converts: dist_x depends only on xh (+rx computed on s2)
    cudaEventRecord(ev_cvt, 0);
    cudaStreamWaitEvent(s2, ev_cvt, 0);
    rownorm_kernel<<<N_ROWS, 256, 0, s2>>>(x, rx, DIM);
    dist_x_kernel<<<NBLK_DIST, 256, smem_dist, s2>>>(xh, rx, dx);

#define TCL(ah_, al_, wh_, wl_, b_, c_, oh_, ol_, N_, K_, wf, ws) \
    tc_gemm_bias_lrelu<<<dim3((N_) / 128, NB), 256, smem_gemm>>>( \
        ah_, al_, wh_, wl_, b_, c_, oh_, ol_, N_, (K_) / 64, wf, ws)
    // encoder (main stream, concurrent with dist_x)
    TCL(xh,  xl,  we1h, we1l, be1, (float*)nullptr, a1h, a1l, H1,  DIM, 0, 1);
    TCL(a1h, a1l, we2h, we2l, be2, (float*)nullptr, a2h, a2l, H2,  H1,  0, 1);
    TCL(a2h, a2l, we3h, we3l, be3, lat,             lh,  ll,  LAT, H2,  1, 1);
    rownorm_kernel<<<N_ROWS, 128>>>(lat, rl, LAT);
    cudaEventRecord(ev_lat, 0);

    // decoder (main stream, concurrent with dist_lat)
    TCL(lh,  ll,  wd1h, wd1l, bd1, (float*)nullptr, a4h, a4l, H2,  LAT, 0, 1);
    TCL(a4h, a4l, wd2h, wd2l, bd2, (float*)nullptr, a5h, a5l, H1,  H2,  0, 1);
    TCL(a5h, a5l, wd3h, wd3l, bd3, out,  (__nv_bfloat16*)nullptr, (__nv_bfloat16*)nullptr, DIM, H1, 1, 0);
#undef TCL

    // dist_lat on s2 after latent ready (and after dist_x, same stream)
    cudaStreamWaitEvent(s2, ev_lat, 0);
    dist_lat_kernel<<<NBLK_DIST, 256, smem_dist, s2>>>(lh, rl, dx);
    cudaEventRecord(ev_join, s2);

    cudaStreamWaitEvent(0, ev_join, 0);
    finalize_kernel<<<1, 1>>>(out, (long long)out_size - 1);
}

// round 15
// speedup vs baseline: 1.1437x; 1.1437x over previous
#include <cuda_runtime.h>
#include <cuda_bf16.h>
#include <math.h>
#include <stdint.h>

#define N_ROWS 4096
#define DIM    1024
#define H1     512
#define H2     256
#define LAT    128
#define SLOPE  0.01f
#define NB     (N_ROWS / 128)
#define NBJ    (N_ROWS / 256)
#define NKC_X  (DIM / 64)
#define NKC_L  (LAT / 64)
#define TILE_ELEMS 8192
#define TILE_BYTES 16384
#define NCH_DIST (NKC_L + NKC_X)

#if defined(__CUDA_ARCH_FEAT_SM103_ALL) || defined(__CUDA_ARCH_FEAT_SM100_ALL) || defined(__CUDA_ARCH_FEAT_SM101_ALL)
#define HAS_TCGEN05 1
#else
#define HAS_TCGEN05 0
#endif

// -------- scratch --------
__device__ float g_lat[N_ROWS * LAT];
__device__ float g_rx[N_ROWS];
__device__ float g_rl[N_ROWS];
__device__ double g_stats[5];
__device__ __align__(16) __nv_bfloat16 g_xh[NB * NKC_X * TILE_ELEMS];
__device__ __align__(16) __nv_bfloat16 g_xl[NB * NKC_X * TILE_ELEMS];
__device__ __align__(16) __nv_bfloat16 g_lh[NB * NKC_L * TILE_ELEMS];
__device__ __align__(16) __nv_bfloat16 g_ll[NB * NKC_L * TILE_ELEMS];
__device__ __align__(16) __nv_bfloat16 g_a1h[N_ROWS * H1], g_a1l[N_ROWS * H1];
__device__ __align__(16) __nv_bfloat16 g_a2h[N_ROWS * H2], g_a2l[N_ROWS * H2];
__device__ __align__(16) __nv_bfloat16 g_a4h[N_ROWS * H2], g_a4l[N_ROWS * H2];
__device__ __align__(16) __nv_bfloat16 g_a5h[N_ROWS * H1], g_a5l[N_ROWS * H1];
__device__ __align__(16) __nv_bfloat16 g_we1h[H1 * DIM], g_we1l[H1 * DIM];
__device__ __align__(16) __nv_bfloat16 g_we2h[H2 * H1],  g_we2l[H2 * H1];
__device__ __align__(16) __nv_bfloat16 g_we3h[LAT * H2], g_we3l[LAT * H2];
__device__ __align__(16) __nv_bfloat16 g_wd1h[H2 * LAT], g_wd1l[H2 * LAT];
__device__ __align__(16) __nv_bfloat16 g_wd2h[H1 * H2],  g_wd2l[H1 * H2];
__device__ __align__(16) __nv_bfloat16 g_wd3h[DIM * H1], g_wd3l[DIM * H1];

__global__ void zero_stats_kernel() {
    if (threadIdx.x < 5) g_stats[threadIdx.x] = 0.0;
}

// ================= PTX helpers =================
__device__ __forceinline__ uint32_t smem_u32(const void* p) {
    uint32_t a;
    asm("{ .reg .u64 t; cvta.to.shared.u64 t, %1; cvt.u32.u64 %0, t; }" : "=r"(a) : "l"(p));
    return a;
}
__device__ __forceinline__ uint32_t elect_one() {
    uint32_t p;
    asm volatile("{\n\t.reg .pred p;\n\telect.sync _|p, 0xFFFFFFFF;\n\tselp.b32 %0, 1, 0, p;\n\t}" : "=r"(p));
    return p;
}
#define MBAR_INIT(mbar, c) \
    asm volatile("mbarrier.init.shared.b64 [%0], %1;" :: "r"(mbar), "r"((uint32_t)(c)) : "memory")
#define MBAR_INVAL(mbar) \
    asm volatile("mbarrier.inval.shared.b64 [%0];" :: "r"(mbar) : "memory")
#define MBAR_ARRIVE(mbar) \
    asm volatile("mbarrier.arrive.shared.b64 _, [%0];" :: "r"(mbar) : "memory")
#define MBAR_EXPECT_TX(mbar, bytes) \
    asm volatile("mbarrier.arrive.expect_tx.shared.b64 _, [%0], %1;" \
                 :: "r"(mbar), "r"((uint32_t)(bytes)) : "memory")

__device__ __forceinline__ void mbar_wait_parity(uint32_t mbar, uint32_t parity) {
    uint32_t done;
    asm volatile("{\n\t.reg .pred p;\n\t"
                 "mbarrier.try_wait.parity.acquire.cta.shared::cta.b64 p, [%1], %2;\n\t"
                 "selp.b32 %0, 1, 0, p;\n\t}" : "=r"(done) : "r"(mbar), "r"(parity) : "memory");
    if (!done) {
        asm volatile("{\n\t.reg .pred P1;\n\t"
                     "WL_%=:\n\t"
                     "mbarrier.try_wait.parity.acquire.cta.shared::cta.b64 P1, [%0], %1, 0x989680;\n\t"
                     "@P1 bra.uni WD_%=;\n\t"
                     "bra.uni WL_%=;\n\t"
                     "WD_%=:\n\t}" :: "r"(mbar), "r"(parity) : "memory");
    }
}

#if HAS_TCGEN05
#define TC_ALLOC(smem_addr, n) \
    asm volatile("tcgen05.alloc.cta_group::1.sync.aligned.shared::cta.b32 [%0], %1;" \
                 :: "r"(smem_addr), "r"((uint32_t)(n)) : "memory")
#define TC_DEALLOC(tmem, n) \
    asm volatile("tcgen05.dealloc.cta_group::1.sync.aligned.b32 %0, %1;" :: "r"(tmem), "r"((uint32_t)(n)))
#define TC_COMMIT(mbar) \
    asm volatile("tcgen05.commit.cta_group::1.mbarrier::arrive::one.shared::cluster.b64 [%0];" \
                 :: "r"(mbar) : "memory")
#define TC_FENCE_AFTER()  asm volatile("tcgen05.fence::after_thread_sync;" ::: "memory")
#define TC_WAIT_LD()      asm volatile("tcgen05.wait::ld.sync.aligned;" ::: "memory")
#define BULK_G2S(dst, src, bytes, mbar) \
    asm volatile("cp.async.bulk.shared::cta.global.mbarrier::complete_tx::bytes [%0], [%1], %2, [%3];" \
                 :: "r"(dst), "l"(src), "r"((uint32_t)(bytes)), "r"(mbar) : "memory")

__device__ __forceinline__ void mma_f16_ss(uint32_t d_tmem, uint64_t a_desc, uint64_t b_desc,
                                           uint32_t idesc, bool accum) {
    uint32_t en = accum ? 1u : 0u;
    asm volatile("{\n\t.reg .pred p;\n\t"
                 "setp.ne.u32 p, %5, 0;\n\t"
                 "tcgen05.mma.cta_group::1.kind::f16 [%0], %1, %2, %3, {%4, %4, %4, %4}, p;\n\t}"
                 :: "r"(d_tmem), "l"(a_desc), "l"(b_desc), "r"(idesc), "r"(0u), "r"(en)
                 : "memory");
}

#define LDTM32(r, addr) \
    asm volatile("tcgen05.ld.sync.aligned.32x32b.x32.b32 " \
        "{%0, %1, %2, %3, %4, %5, %6, %7, %8, %9, %10, %11, %12, %13, %14, %15, " \
        " %16, %17, %18, %19, %20, %21, %22, %23, %24, %25, %26, %27, %28, %29, %30, %31}, [%32];" \
        : "=r"((r)[0]), "=r"((r)[1]), "=r"((r)[2]), "=r"((r)[3]), \
          "=r"((r)[4]), "=r"((r)[5]), "=r"((r)[6]), "=r"((r)[7]), \
          "=r"((r)[8]), "=r"((r)[9]), "=r"((r)[10]), "=r"((r)[11]), \
          "=r"((r)[12]), "=r"((r)[13]), "=r"((r)[14]), "=r"((r)[15]), \
          "=r"((r)[16]), "=r"((r)[17]), "=r"((r)[18]), "=r"((r)[19]), \
          "=r"((r)[20]), "=r"((r)[21]), "=r"((r)[22]), "=r"((r)[23]), \
          "=r"((r)[24]), "=r"((r)[25]), "=r"((r)[26]), "=r"((r)[27]), \
          "=r"((r)[28]), "=r"((r)[29]), "=r"((r)[30]), "=r"((r)[31]) \
        : "r"(addr))

static __device__ __forceinline__ uint64_t make_desc(uint32_t addr) {
    const uint64_t base = (uint64_t(2) << 61) | (uint64_t(1) << 46)
                        | (uint64_t(64) << 32) | (uint64_t(1) << 16);
    return base | ((uint64_t)(addr >> 4) & 0x3FFF);
}
#define IDESC_N128 0x8200490u
#define IDESC_N256 0x8400490u
#endif // HAS_TCGEN05

// ================= row squared-norms =================
__global__ void rownorm_kernel(const float* __restrict__ X, float* __restrict__ r, int K) {
    int row = blockIdx.x;
    const float* p = X + (size_t)row * K;
    float s = 0.f;
    for (int k = threadIdx.x; k < K; k += blockDim.x) {
        float v = p[k];
        s += v * v;
    }
#pragma unroll
    for (int off = 16; off > 0; off >>= 1)
        s += __shfl_down_sync(0xffffffffu, s, off);
    __shared__ float sm[32];
    int lane = threadIdx.x & 31, wid = threadIdx.x >> 5;
    if (lane == 0) sm[wid] = s;
    __syncthreads();
    if (wid == 0) {
        int nw = blockDim.x >> 5;
        float v = (lane < nw) ? sm[lane] : 0.f;
#pragma unroll
        for (int off = 16; off > 0; off >>= 1)
            v += __shfl_down_sync(0xffffffffu, v, off);
        if (lane == 0) r[row] = v;
    }
}

// ================= fused split-convert =================
struct alignas(16) bf16x8 { __nv_bfloat16 v[8]; };
struct CvtSeg { const float* src; __nv_bfloat16* dh; __nv_bfloat16* dl; int K; unsigned base; };
struct CvtArgs { CvtSeg seg[7]; unsigned total; };

__global__ void convert_all_kernel(CvtArgs args) {
    unsigned gid = blockIdx.x * blockDim.x + threadIdx.x;
    if (gid >= args.total) return;
    int si = 0;
#pragma unroll
    for (int i = 1; i < 7; i++)
        if (gid >= args.seg[i].base) si = i;
    const CvtSeg s = args.seg[si];
    unsigned idx = gid - s.base;
    int K = s.K, gpr = K >> 3, nkc = K >> 6;
    int r  = idx / gpr;
    int k0 = (idx - r * gpr) * 8;

    const float* p = s.src + (size_t)r * K + k0;
    float4 v0 = *(const float4*)p;
    float4 v1 = *(const float4*)(p + 4);
    float f[8] = {v0.x, v0.y, v0.z, v0.w, v1.x, v1.y, v1.z, v1.w};

    bf16x8 ph, pl;
#pragma unroll
    for (int m = 0; m < 8; m++) {
        __nv_bfloat16 h = __float2bfloat16(f[m]);
        ph.v[m] = h;
        pl.v[m] = __float2bfloat16(f[m] - __bfloat162float(h));
    }

    int rb = r >> 7, lr = r & 127;
    int kc = k0 >> 6, g = (k0 & 63) >> 3;
    int gsw = g ^ (lr & 7);
    size_t off = (((size_t)rb * nkc + kc) * 128 + lr) * 64 + gsw * 8;
    *(bf16x8*)&s.dh[off] = ph;
    *(bf16x8*)&s.dl[off] = pl;
}

// ================= tcgen05 GEMM + bias + LeakyReLU (R9 config) =================
#define GS 3
__global__ void __launch_bounds__(256, 1)
tc_gemm_bias_lrelu(const __nv_bfloat16* __restrict__ ah, const __nv_bfloat16* __restrict__ al,
                   const __nv_bfloat16* __restrict__ wh, const __nv_bfloat16* __restrict__ wl,
                   const float* __restrict__ bias,
                   float* __restrict__ Cfp,
                   __nv_bfloat16* __restrict__ oh, __nv_bfloat16* __restrict__ ol,
                   int N, int NC, int write_fp32, int write_split) {
    const int nb = blockIdx.x, mb = blockIdx.y;
    const int n0 = nb * 128, m0 = mb * 128;
    const int t = threadIdx.x;

#if HAS_TCGEN05
    extern __shared__ char dsm_raw[];
    char* dsm = (char*)(((uintptr_t)dsm_raw + 1023) & ~(uintptr_t)1023);
    __shared__ __align__(8) unsigned long long s_mbar[2 * GS + 1];
    __shared__ uint32_t s_tmem;

    const int wid = t >> 5;
    const int lid = t & 31;
    const uint32_t mb0   = smem_u32(&s_mbar[0]);
    const uint32_t donem = mb0 + 2 * GS * 8;
#define FULLB(b)  (mb0 + (uint32_t)(b) * 8)
#define EMPTYB(b) (mb0 + (uint32_t)(GS + (b)) * 8)

    if (wid == 0) TC_ALLOC(smem_u32(&s_tmem), 128);
    if (t == 0) {
        for (int k = 0; k < 2 * GS; k++) MBAR_INIT(mb0 + k * 8, 1);
        MBAR_INIT(donem, 1);
    }
    __syncthreads();
    const uint32_t D = s_tmem;
    const uint32_t smem_base = smem_u32(dsm);

    if (wid == 0 && elect_one()) {
        const int np = (NC < GS) ? NC : GS;
        for (int k = 0; k < np; k++) {
            const uint32_t bufb = smem_base + (uint32_t)k * 65536;
            MBAR_EXPECT_TX(FULLB(k), 65536);
            BULK_G2S(bufb,         (const char*)(ah + ((size_t)mb * NC + k) * TILE_ELEMS), TILE_BYTES, FULLB(k));
            BULK_G2S(bufb + 16384, (const char*)(al + ((size_t)mb * NC + k) * TILE_ELEMS), TILE_BYTES, FULLB(k));
            BULK_G2S(bufb + 32768, (const char*)(wh + ((size_t)nb * NC + k) * TILE_ELEMS), TILE_BYTES, FULLB(k));
            BULK_G2S(bufb + 49152, (const char*)(wl + ((size_t)nb * NC + k) * TILE_ELEMS), TILE_BYTES, FULLB(k));
        }
#pragma unroll 1
        for (int n = 0; n < NC; n++) {
            const int b = n % GS, q = n / GS;
            const uint32_t bufb = smem_base + (uint32_t)b * 65536;
            mbar_wait_parity(FULLB(b), (uint32_t)(q & 1));

            uint64_t dAh = make_desc(bufb);
            uint64_t dAl = make_desc(bufb + 16384);
            uint64_t dWh = make_desc(bufb + 32768);
            uint64_t dWl = make_desc(bufb + 49152);
#pragma unroll
            for (int s = 0; s < 4; s++) {
                uint64_t off = s * 2;
                mma_f16_ss(D, dAh + off, dWh + off, IDESC_N128, !(n == 0 && s == 0));
                mma_f16_ss(D, dAh + off, dWl + off, IDESC_N128, true);
                mma_f16_ss(D, dAl + off, dWh + off, IDESC_N128, true);
            }
            TC_COMMIT(EMPTYB(b));

            if (n + GS < NC) {
                const int m = n + GS;
                mbar_wait_parity(EMPTYB(b), (uint32_t)(q & 1));
                MBAR_EXPECT_TX(FULLB(b), 65536);
                BULK_G2S(bufb,         (const char*)(ah + ((size_t)mb * NC + m) * TILE_ELEMS), TILE_BYTES, FULLB(b));
                BULK_G2S(bufb + 16384, (const char*)(al + ((size_t)mb * NC + m) * TILE_ELEMS), TILE_BYTES, FULLB(b));
                BULK_G2S(bufb + 32768, (const char*)(wh + ((size_t)nb * NC + m) * TILE_ELEMS), TILE_BYTES, FULLB(b));
                BULK_G2S(bufb + 49152, (const char*)(wl + ((size_t)nb * NC + m) * TILE_ELEMS), TILE_BYTES, FULLB(b));
            }
        }
        for (int n = (NC > GS ? NC - GS : 0); n < NC; n++)
            mbar_wait_parity(EMPTYB(n % GS), (uint32_t)((n / GS) & 1));
        MBAR_ARRIVE(donem);
    }
    mbar_wait_parity(donem, 0u);
    TC_FENCE_AFTER();

    const int wg  = wid >> 2;
    const int sub = wid & 3;
    const int lr  = sub * 32 + lid;
    const int m   = m0 + lr;
    const int nkc_out = N >> 6;

#pragma unroll
    for (int bb = 0; bb < 2; bb++) {
        const int colbase = wg * 64 + bb * 32;
        uint32_t dr[32];
        LDTM32(dr, D + colbase);
        TC_WAIT_LD();
        float v[32];
#pragma unroll
        for (int c = 0; c < 32; c++) {
            float x = __uint_as_float(dr[c]) + __ldg(&bias[n0 + colbase + c]);
            v[c] = (x >= 0.f) ? x : SLOPE * x;
        }
        if (write_fp32) {
#pragma unroll
            for (int c = 0; c < 32; c++)
                Cfp[(size_t)m * N + n0 + colbase + c] = v[c];
        }
        if (write_split) {
#pragma unroll
            for (int g8 = 0; g8 < 4; g8++) {
                int nn = n0 + colbase + g8 * 8;
                int kc = nn >> 6, g = (nn & 63) >> 3;
                int gsw = g ^ (lr & 7);
                size_t off = (((size_t)mb * nkc_out + kc) * 128 + lr) * 64 + gsw * 8;
                bf16x8 ph, pl;
#pragma unroll
                for (int e = 0; e < 8; e++) {
                    float x = v[g8 * 8 + e];
                    __nv_bfloat16 h = __float2bfloat16(x);
                    ph.v[e] = h;
                    pl.v[e] = __float2bfloat16(x - __bfloat162float(h));
                }
                *(bf16x8*)&oh[off] = ph;
                *(bf16x8*)&ol[off] = pl;
            }
        }
    }

    __syncthreads();
    if (t == 0) {
        for (int k = 0; k < 2 * GS; k++) MBAR_INVAL(mb0 + k * 8);
        MBAR_INVAL(donem);
    }
    __syncthreads();
    if (wid == 0) TC_DEALLOC(D, 128);
#undef FULLB
#undef EMPTYB

#else
    const int K = NC * 64;
    const int lr0 = t & 127;
    const int m = m0 + lr0;
    const int jh = (t >> 7) * 64;
    const int nkc_out = N >> 6;
    for (int jj = 0; jj < 64; jj++) {
        int nn = n0 + jh + jj;
        int wrb = nn >> 7, wlr = nn & 127;
        float acc = 0.f;
        for (int k = 0; k < K; k++) {
            int kc = k >> 6, g = (k & 63) >> 3, e = k & 7;
            size_t aoff = (((size_t)mb * NC + kc) * 128 + lr0) * 64 + (size_t)((g ^ (lr0 & 7)) * 8 + e);
            size_t woff = (((size_t)wrb * NC + kc) * 128 + wlr) * 64 + (size_t)((g ^ (wlr & 7)) * 8 + e);
            float av = __bfloat162float(ah[aoff]) + __bfloat162float(al[aoff]);
            float wv = __bfloat162float(wh[woff]) + __bfloat162float(wl[woff]);
            acc += av * wv;
        }
        float x = acc + bias[nn];
        x = (x >= 0.f) ? x : SLOPE * x;
        if (write_fp32) Cfp[(size_t)m * N + nn] = x;
        if (write_split) {
            __nv_bfloat16 h = __float2bfloat16(x);
            int kc = nn >> 6, g = (nn & 63) >> 3;
            size_t off = (((size_t)mb * nkc_out + kc) * 128 + lr0) * 64 + (size_t)((g ^ (lr0 & 7)) * 8 + (nn & 7));
            oh[off] = h;
            ol[off] = __float2bfloat16(x - __bfloat162float(h));
        }
    }
#endif
}

// ================= fused Gram + distance + stats, 128x256 tiles, depth-4 =================
#define DS 4
__global__ void __launch_bounds__(256, 1)
dist_stats_tc_kernel(const __nv_bfloat16* __restrict__ xh,
                     const __nv_bfloat16* __restrict__ lh,
                     const float* __restrict__ rx,
                     const float* __restrict__ rl) {
    int b = blockIdx.x;
    int bi = 0, rem = b;
    while (rem >= NBJ - (bi >> 1)) { rem -= NBJ - (bi >> 1); bi++; }
    int jb2 = (bi >> 1) + rem;
    const bool dcheck = (jb2 == (bi >> 1));
    const int i0 = bi * 128, j0 = jb2 * 256;

    __shared__ double red[256];
    const int t = threadIdx.x;

    float fs1 = 0.f, fs2 = 0.f, fs11 = 0.f, fs22 = 0.f, fs12 = 0.f;

#if HAS_TCGEN05
    extern __shared__ char dsm_raw[];
    char* dsm = (char*)(((uintptr_t)dsm_raw + 1023) & ~(uintptr_t)1023);
    __shared__ __align__(8) unsigned long long s_mbar[2 * DS + 1];
    __shared__ uint32_t s_tmem;

    const int wid = t >> 5;
    const int lid = t & 31;
    const uint32_t mb0   = smem_u32(&s_mbar[0]);
    const uint32_t donem = mb0 + 2 * DS * 8;
#define FULLB(b)  (mb0 + (uint32_t)(b) * 8)
#define EMPTYB(b) (mb0 + (uint32_t)(DS + (b)) * 8)

    if (wid == 0) TC_ALLOC(smem_u32(&s_tmem), 512);
    if (t == 0) {
        for (int k = 0; k < 2 * DS; k++) MBAR_INIT(mb0 + k * 8, 1);
        MBAR_INIT(donem, 1);
    }
    __syncthreads();
    const uint32_t tmem = s_tmem;
    const uint32_t D_X = tmem, D_L = tmem + 256;
    const uint32_t smem_base = smem_u32(dsm);

    if (wid == 0 && elect_one()) {
        auto docopy = [&](int n, int bsel) {
            const __nv_bfloat16 *base; int nkc, arow;
            if (n < NKC_L) { base = lh; nkc = NKC_L; arow = n; }
            else           { base = xh; nkc = NKC_X; arow = n - NKC_L; }
            const uint32_t bufb = smem_base + (uint32_t)bsel * 49152;
            const uint32_t fb = FULLB(bsel);
            MBAR_EXPECT_TX(fb, 49152);
            BULK_G2S(bufb, (const char*)(base + ((size_t)bi * nkc + arow) * TILE_ELEMS), TILE_BYTES, fb);
            BULK_G2S(bufb + 16384, (const char*)(base + ((size_t)(jb2 * 2) * nkc + arow) * TILE_ELEMS), TILE_BYTES, fb);
            BULK_G2S(bufb + 32768, (const char*)(base + ((size_t)(jb2 * 2 + 1) * nkc + arow) * TILE_ELEMS), TILE_BYTES, fb);
        };
        for (int k = 0; k < DS; k++) docopy(k, k);

#pragma unroll 1
        for (int n = 0; n < NCH_DIST; n++) {
            const int bsel = n % DS, q = n / DS;
            const uint32_t bufb = smem_base + (uint32_t)bsel * 49152;
            mbar_wait_parity(FULLB(bsel), (uint32_t)(q & 1));

            const uint32_t Dacc = (n < NKC_L) ? D_L : D_X;
            const bool first = (n == 0) || (n == NKC_L);
            uint64_t dA = make_desc(bufb), dB = make_desc(bufb + 16384);
#pragma unroll
            for (int s = 0; s < 4; s++)
                mma_f16_ss(Dacc, dA + s * 2, dB + s * 2, IDESC_N256, !(first && s == 0));
            TC_COMMIT(EMPTYB(bsel));

            if (n + DS < NCH_DIST) {
                mbar_wait_parity(EMPTYB(bsel), (uint32_t)(q & 1));
                docopy(n + DS, bsel);
            }
        }
        for (int n = NCH_DIST - DS; n < NCH_DIST; n++)
            mbar_wait_parity(EMPTYB(n % DS), (uint32_t)((n / DS) & 1));
        MBAR_ARRIVE(donem);
    }
    mbar_wait_parity(donem, 0u);
    TC_FENCE_AFTER();

    const int wg  = wid >> 2;
    const int sub = wid & 3;
    const int i = i0 + sub * 32 + lid;
    const float rxi = __ldg(&rx[i]);
    const float rli = __ldg(&rl[i]);

#pragma unroll 1
    for (int bb = 0; bb < 4; bb++) {
        const int colbase = wg * 128 + bb * 32;
        uint32_t xg[32], lg[32];
        LDTM32(xg, D_X + colbase);
        LDTM32(lg, D_L + colbase);
        TC_WAIT_LD();
#pragma unroll
        for (int c = 0; c < 32; c++) {
            int j = j0 + colbase + c;
            if (!dcheck || j > i) {
                float gx = __uint_as_float(xg[c]);
                float gl = __uint_as_float(lg[c]);
                float sqx = rxi + __ldg(&rx[j]) - 2.f * gx;
                float sql = rli + __ldg(&rl[j]) - 2.f * gl;
                float dx = sqrtf(fmaxf(sqx, 0.f));
                float dv = sqrtf(fmaxf(sql, 0.f));
                fs1  += dx;
                fs2  += dv;
                fs11 += dx * dx;
                fs22 += dv * dv;
                fs12 += dx * dv;
            }
        }
    }

    __syncthreads();
    if (t == 0) {
        for (int k = 0; k < 2 * DS; k++) MBAR_INVAL(mb0 + k * 8);
        MBAR_INVAL(donem);
    }
    __syncthreads();
    if (wid == 0) TC_DEALLOC(tmem, 512);
#undef FULLB
#undef EMPTYB

#else  // fallback: dequant fp32 hi-only
    const int tx = (t & 15) * 16;
    const int ty = (t >> 4) * 8;
    for (int ii = 0; ii < 8; ii++) {
        int i = i0 + ty + ii;
        float rxi = rx[i], rli = rl[i];
        int ib = i >> 7, ilr = i & 127;
        for (int jj = 0; jj < 16; jj++) {
            int j = j0 + tx + jj;
            if (dcheck && j <= i) continue;
            int jb = j >> 7, jlr = j & 127;
            float gx = 0.f, gl = 0.f;
            for (int k = 0; k < DIM; k++) {
                int kc = k >> 6, g = (k & 63) >> 3, e = k & 7;
                size_t ioff = (((size_t)ib * NKC_X + kc) * 128 + ilr) * 64 + (size_t)((g ^ (ilr & 7)) * 8 + e);
                size_t joff = (((size_t)jb * NKC_X + kc) * 128 + jlr) * 64 + (size_t)((g ^ (jlr & 7)) * 8 + e);
                gx += __bfloat162float(xh[ioff]) * __bfloat162float(xh[joff]);
            }
            for (int k = 0; k < LAT; k++) {
                int kc = k >> 6, g = (k & 63) >> 3, e = k & 7;
                size_t ioff = (((size_t)ib * NKC_L + kc) * 128 + ilr) * 64 + (size_t)((g ^ (ilr & 7)) * 8 + e);
                size_t joff = (((size_t)jb * NKC_L + kc) * 128 + jlr) * 64 + (size_t)((g ^ (jlr & 7)) * 8 + e);
                gl += __bfloat162float(lh[ioff]) * __bfloat162float(lh[joff]);
            }
            float dx = sqrtf(fmaxf(rxi + rx[j] - 2.f * gx, 0.f));
            float dv = sqrtf(fmaxf(rli + rl[j] - 2.f * gl, 0.f));
            fs1 += dx; fs2 += dv; fs11 += dx * dx; fs22 += dv * dv; fs12 += dx * dv;
        }
    }
#endif

    float vals[5] = {fs1, fs2, fs11, fs22, fs12};
#pragma unroll
    for (int v = 0; v < 5; v++) {
        red[t] = (double)vals[v];
        __syncthreads();
        for (int off = 128; off > 0; off >>= 1) {
            if (t < off) red[t] += red[t + off];
            __syncthreads();
        }
        if (t == 0) atomicAdd(&g_stats[v], red[0]);
        __syncthreads();
    }
}

__global__ void finalize_kernel(float* __restrict__ out, long long idx) {
    const double n = (double)N_ROWS * (double)N_ROWS;
    double s1  = 2.0 * g_stats[0];
    double s2  = 2.0 * g_stats[1];
    double s11 = 2.0 * g_stats[2];
    double s22 = 2.0 * g_stats[3];
    double s12 = 2.0 * g_stats[4];
    double m1 = s1 / n;
    double m2 = s2 / n;
    double v1 = (s11 - n * m1 * m1) / (n - 1.0);
    double v2 = (s22 - n * m2 * m2) / (n - 1.0);
    double cov = s12 / n - m1 * m2;
    out[idx] = (float)(cov / sqrt(v1 * v2));
}

extern "C" void kernel_launch(void* const* d_in, const int* in_sizes, int n_in,
                              void* d_out, int out_size) {
    const float* x   = (const float*)d_in[0];
    const float* We1 = (const float*)d_in[1];
    const float* be1 = (const float*)d_in[2];
    const float* We2 = (const float*)d_in[3];
    const float* be2 = (const float*)d_in[4];
    const float* We3 = (const float*)d_in[5];
    const float* be3 = (const float*)d_in[6];
    const float* Wd1 = (const float*)d_in[7];
    const float* bd1 = (const float*)d_in[8];
    const float* Wd2 = (const float*)d_in[9];
    const float* bd2 = (const float*)d_in[10];
    const float* Wd3 = (const float*)d_in[11];
    const float* bd3 = (const float*)d_in[12];
    float* out = (float*)d_out;

    float* lat = nullptr; cudaGetSymbolAddress((void**)&lat, g_lat);
    float* rx  = nullptr; cudaGetSymbolAddress((void**)&rx,  g_rx);
    float* rl  = nullptr; cudaGetSymbolAddress((void**)&rl,  g_rl);
#define SYM(T, v, s) T* v = nullptr; cudaGetSymbolAddress((void**)&v, s)
    SYM(__nv_bfloat16, xh, g_xh);   SYM(__nv_bfloat16, xl, g_xl);
    SYM(__nv_bfloat16, lh, g_lh);   SYM(__nv_bfloat16, ll, g_ll);
    SYM(__nv_bfloat16, a1h, g_a1h); SYM(__nv_bfloat16, a1l, g_a1l);
    SYM(__nv_bfloat16, a2h, g_a2h); SYM(__nv_bfloat16, a2l, g_a2l);
    SYM(__nv_bfloat16, a4h, g_a4h); SYM(__nv_bfloat16, a4l, g_a4l);
    SYM(__nv_bfloat16, a5h, g_a5h); SYM(__nv_bfloat16, a5l, g_a5l);
    SYM(__nv_bfloat16, we1h, g_we1h); SYM(__nv_bfloat16, we1l, g_we1l);
    SYM(__nv_bfloat16, we2h, g_we2h); SYM(__nv_bfloat16, we2l, g_we2l);
    SYM(__nv_bfloat16, we3h, g_we3h); SYM(__nv_bfloat16, we3l, g_we3l);
    SYM(__nv_bfloat16, wd1h, g_wd1h); SYM(__nv_bfloat16, wd1l, g_wd1l);
    SYM(__nv_bfloat16, wd2h, g_wd2h); SYM(__nv_bfloat16, wd2l, g_wd2l);
    SYM(__nv_bfloat16, wd3h, g_wd3h); SYM(__nv_bfloat16, wd3l, g_wd3l);
#undef SYM

    static cudaStream_t s2 = nullptr;
    static cudaEvent_t ev_cvt = nullptr, ev_fork = nullptr, ev_join = nullptr;
    if (s2 == nullptr) {
        cudaStreamCreateWithFlags(&s2, cudaStreamNonBlocking);
        cudaEventCreateWithFlags(&ev_cvt, cudaEventDisableTiming);
        cudaEventCreateWithFlags(&ev_fork, cudaEventDisableTiming);
        cudaEventCreateWithFlags(&ev_join, cudaEventDisableTiming);
    }

    zero_stats_kernel<<<1, 32>>>();

    {
        CvtArgs a;
        unsigned base = 0;
        auto set = [&](int i, const float* src, __nv_bfloat16* dh, __nv_bfloat16* dl,
                       int rows, int K) {
            a.seg[i] = {src, dh, dl, K, base};
            base += (unsigned)(rows * K / 8);
        };
        set(0, x,   xh,   xl,   N_ROWS, DIM);
        set(1, We1, we1h, we1l, H1,  DIM);
        set(2, We2, we2h, we2l, H2,  H1);
        set(3, We3, we3h, we3l, LAT, H2);
        set(4, Wd1, wd1h, wd1l, H2,  LAT);
        set(5, Wd2, wd2h, wd2l, H1,  H2);
        set(6, Wd3, wd3h, wd3l, DIM, H1);
        a.total = base;
        convert_all_kernel<<<(base + 255) / 256, 256>>>(a);
    }
    // rownorm(x) off the critical path: only dist consumes it
    cudaEventRecord(ev_cvt, 0);
    cudaStreamWaitEvent(s2, ev_cvt, 0);
    rownorm_kernel<<<N_ROWS, 256, 0, s2>>>(x, rx, DIM);

    const int smem_gemm = GS * 65536 + 1024;
    const int smem_dist = DS * 49152 + 1024;
    cudaFuncSetAttribute(tc_gemm_bias_lrelu, cudaFuncAttributeMaxDynamicSharedMemorySize, smem_gemm);
    cudaFuncSetAttribute(dist_stats_tc_kernel, cudaFuncAttributeMaxDynamicSharedMemorySize, smem_dist);

#define TCL(ah_, al_, wh_, wl_, b_, c_, oh_, ol_, N_, K_, wf, ws) \
    tc_gemm_bias_lrelu<<<dim3((N_) / 128, NB), 256, smem_gemm>>>( \
        ah_, al_, wh_, wl_, b_, c_, oh_, ol_, N_, (K_) / 64, wf, ws)
    // encoder
    TCL(xh,  xl,  we1h, we1l, be1, (float*)nullptr, a1h, a1l, H1,  DIM, 0, 1);
    TCL(a1h, a1l, we2h, we2l, be2, (float*)nullptr, a2h, a2l, H2,  H1,  0, 1);
    TCL(a2h, a2l, we3h, we3l, be3, lat,             lh,  ll,  LAT, H2,  1, 1);
    rownorm_kernel<<<N_ROWS, 128>>>(lat, rl, LAT);

    // fork: dist (combined) depends on xh, lh, rx, rl -> concurrent with decoder
    cudaEventRecord(ev_fork, 0);
    cudaStreamWaitEvent(s2, ev_fork, 0);
    {
        int nblk = 0;
        for (int bi = 0; bi < NB; bi++) nblk += NBJ - (bi >> 1);
        dist_stats_tc_kernel<<<nblk, 256, smem_dist, s2>>>(xh, lh, rx, rl);
    }
    cudaEventRecord(ev_join, s2);

    // decoder on main stream, concurrent with dist
    TCL(lh,  ll,  wd1h, wd1l, bd1, (float*)nullptr, a4h, a4l, H2,  LAT, 0, 1);
    TCL(a4h, a4l, wd2h, wd2l, bd2, (float*)nullptr, a5h, a5l, H1,  H2,  0, 1);
    TCL(a5h, a5l, wd3h, wd3l, bd3, out,  (__nv_bfloat16*)nullptr, (__nv_bfloat16*)nullptr, DIM, H1, 1, 0);
#undef TCL

    cudaStreamWaitEvent(0, ev_join, 0);
    finalize_kernel<<<1, 1>>>(out, (long long)out_size - 1);
}

// round 16
// speedup vs baseline: 1.2025x; 1.0514x over previous
#include <cuda_runtime.h>
#include <cuda_bf16.h>
#include <math.h>
#include <stdint.h>

#define N_ROWS 4096
#define DIM    1024
#define H1     512
#define H2     256
#define LAT    128
#define SLOPE  0.01f
#define NB     (N_ROWS / 128)
#define NBJ    (N_ROWS / 256)
#define NKC_X  (DIM / 64)
#define NKC_L  (LAT / 64)
#define TILE_ELEMS 8192
#define TILE_BYTES 16384
#define NCH_DIST (NKC_L + NKC_X)

#if defined(__CUDA_ARCH_FEAT_SM103_ALL) || defined(__CUDA_ARCH_FEAT_SM100_ALL) || defined(__CUDA_ARCH_FEAT_SM101_ALL)
#define HAS_TCGEN05 1
#else
#define HAS_TCGEN05 0
#endif

// -------- scratch --------
__device__ float g_lat[N_ROWS * LAT];
__device__ float g_rx[N_ROWS];
__device__ float g_rl[N_ROWS];
__device__ double g_stats[5];
__device__ __align__(16) __nv_bfloat16 g_xh[NB * NKC_X * TILE_ELEMS];
__device__ __align__(16) __nv_bfloat16 g_xl[NB * NKC_X * TILE_ELEMS];
__device__ __align__(16) __nv_bfloat16 g_lh[NB * NKC_L * TILE_ELEMS];
__device__ __align__(16) __nv_bfloat16 g_ll[NB * NKC_L * TILE_ELEMS];
__device__ __align__(16) __nv_bfloat16 g_a1h[N_ROWS * H1], g_a1l[N_ROWS * H1];
__device__ __align__(16) __nv_bfloat16 g_a2h[N_ROWS * H2], g_a2l[N_ROWS * H2];
__device__ __align__(16) __nv_bfloat16 g_a4h[N_ROWS * H2], g_a4l[N_ROWS * H2];
__device__ __align__(16) __nv_bfloat16 g_a5h[N_ROWS * H1], g_a5l[N_ROWS * H1];
__device__ __align__(16) __nv_bfloat16 g_we1h[H1 * DIM], g_we1l[H1 * DIM];
__device__ __align__(16) __nv_bfloat16 g_we2h[H2 * H1],  g_we2l[H2 * H1];
__device__ __align__(16) __nv_bfloat16 g_we3h[LAT * H2], g_we3l[LAT * H2];
__device__ __align__(16) __nv_bfloat16 g_wd1h[H2 * LAT], g_wd1l[H2 * LAT];
__device__ __align__(16) __nv_bfloat16 g_wd2h[H1 * H2],  g_wd2l[H1 * H2];
__device__ __align__(16) __nv_bfloat16 g_wd3h[DIM * H1], g_wd3l[DIM * H1];

// ================= PTX helpers =================
__device__ __forceinline__ uint32_t smem_u32(const void* p) {
    uint32_t a;
    asm("{ .reg .u64 t; cvta.to.shared.u64 t, %1; cvt.u32.u64 %0, t; }" : "=r"(a) : "l"(p));
    return a;
}
__device__ __forceinline__ uint32_t elect_one() {
    uint32_t p;
    asm volatile("{\n\t.reg .pred p;\n\telect.sync _|p, 0xFFFFFFFF;\n\tselp.b32 %0, 1, 0, p;\n\t}" : "=r"(p));
    return p;
}
#define MBAR_INIT(mbar, c) \
    asm volatile("mbarrier.init.shared.b64 [%0], %1;" :: "r"(mbar), "r"((uint32_t)(c)) : "memory")
#define MBAR_INVAL(mbar) \
    asm volatile("mbarrier.inval.shared.b64 [%0];" :: "r"(mbar) : "memory")
#define MBAR_ARRIVE(mbar) \
    asm volatile("mbarrier.arrive.shared.b64 _, [%0];" :: "r"(mbar) : "memory")
#define MBAR_EXPECT_TX(mbar, bytes) \
    asm volatile("mbarrier.arrive.expect_tx.shared.b64 _, [%0], %1;" \
                 :: "r"(mbar), "r"((uint32_t)(bytes)) : "memory")

__device__ __forceinline__ void mbar_wait_parity(uint32_t mbar, uint32_t parity) {
    uint32_t done;
    asm volatile("{\n\t.reg .pred p;\n\t"
                 "mbarrier.try_wait.parity.acquire.cta.shared::cta.b64 p, [%1], %2;\n\t"
                 "selp.b32 %0, 1, 0, p;\n\t}" : "=r"(done) : "r"(mbar), "r"(parity) : "memory");
    if (!done) {
        asm volatile("{\n\t.reg .pred P1;\n\t"
                     "WL_%=:\n\t"
                     "mbarrier.try_wait.parity.acquire.cta.shared::cta.b64 P1, [%0], %1, 0x989680;\n\t"
                     "@P1 bra.uni WD_%=;\n\t"
                     "bra.uni WL_%=;\n\t"
                     "WD_%=:\n\t}" :: "r"(mbar), "r"(parity) : "memory");
    }
}

#if HAS_TCGEN05
#define TC_ALLOC(smem_addr, n) \
    asm volatile("tcgen05.alloc.cta_group::1.sync.aligned.shared::cta.b32 [%0], %1;" \
                 :: "r"(smem_addr), "r"((uint32_t)(n)) : "memory")
#define TC_DEALLOC(tmem, n) \
    asm volatile("tcgen05.dealloc.cta_group::1.sync.aligned.b32 %0, %1;" :: "r"(tmem), "r"((uint32_t)(n)))
#define TC_COMMIT(mbar) \
    asm volatile("tcgen05.commit.cta_group::1.mbarrier::arrive::one.shared::cluster.b64 [%0];" \
                 :: "r"(mbar) : "memory")
#define TC_FENCE_AFTER()  asm volatile("tcgen05.fence::after_thread_sync;" ::: "memory")
#define TC_WAIT_LD()      asm volatile("tcgen05.wait::ld.sync.aligned;" ::: "memory")
#define BULK_G2S(dst, src, bytes, mbar) \
    asm volatile("cp.async.bulk.shared::cta.global.mbarrier::complete_tx::bytes [%0], [%1], %2, [%3];" \
                 :: "r"(dst), "l"(src), "r"((uint32_t)(bytes)), "r"(mbar) : "memory")
#define BULK_PREF(src, bytes) \
    asm volatile("cp.async.bulk.prefetch.L2.global [%0], %1;" \
                 :: "l"(src), "r"((uint32_t)(bytes)) : "memory")

__device__ __forceinline__ void mma_f16_ss(uint32_t d_tmem, uint64_t a_desc, uint64_t b_desc,
                                           uint32_t idesc, bool accum) {
    uint32_t en = accum ? 1u : 0u;
    asm volatile("{\n\t.reg .pred p;\n\t"
                 "setp.ne.u32 p, %5, 0;\n\t"
                 "tcgen05.mma.cta_group::1.kind::f16 [%0], %1, %2, %3, {%4, %4, %4, %4}, p;\n\t}"
                 :: "r"(d_tmem), "l"(a_desc), "l"(b_desc), "r"(idesc), "r"(0u), "r"(en)
                 : "memory");
}

#define LDTM32(r, addr) \
    asm volatile("tcgen05.ld.sync.aligned.32x32b.x32.b32 " \
        "{%0, %1, %2, %3, %4, %5, %6, %7, %8, %9, %10, %11, %12, %13, %14, %15, " \
        " %16, %17, %18, %19, %20, %21, %22, %23, %24, %25, %26, %27, %28, %29, %30, %31}, [%32];" \
        : "=r"((r)[0]), "=r"((r)[1]), "=r"((r)[2]), "=r"((r)[3]), \
          "=r"((r)[4]), "=r"((r)[5]), "=r"((r)[6]), "=r"((r)[7]), \
          "=r"((r)[8]), "=r"((r)[9]), "=r"((r)[10]), "=r"((r)[11]), \
          "=r"((r)[12]), "=r"((r)[13]), "=r"((r)[14]), "=r"((r)[15]), \
          "=r"((r)[16]), "=r"((r)[17]), "=r"((r)[18]), "=r"((r)[19]), \
          "=r"((r)[20]), "=r"((r)[21]), "=r"((r)[22]), "=r"((r)[23]), \
          "=r"((r)[24]), "=r"((r)[25]), "=r"((r)[26]), "=r"((r)[27]), \
          "=r"((r)[28]), "=r"((r)[29]), "=r"((r)[30]), "=r"((r)[31]) \
        : "r"(addr))

static __device__ __forceinline__ uint64_t make_desc(uint32_t addr) {
    const uint64_t base = (uint64_t(2) << 61) | (uint64_t(1) << 46)
                        | (uint64_t(64) << 32) | (uint64_t(1) << 16);
    return base | ((uint64_t)(addr >> 4) & 0x3FFF);
}
#define IDESC_N128 0x8200490u
#define IDESC_N256 0x8400490u
#endif // HAS_TCGEN05

// ================= row squared-norms (x only now) =================
__global__ void rownorm_kernel(const float* __restrict__ X, float* __restrict__ r, int K) {
    int row = blockIdx.x;
    const float* p = X + (size_t)row * K;
    float s = 0.f;
    for (int k = threadIdx.x; k < K; k += blockDim.x) {
        float v = p[k];
        s += v * v;
    }
#pragma unroll
    for (int off = 16; off > 0; off >>= 1)
        s += __shfl_down_sync(0xffffffffu, s, off);
    __shared__ float sm[32];
    int lane = threadIdx.x & 31, wid = threadIdx.x >> 5;
    if (lane == 0) sm[wid] = s;
    __syncthreads();
    if (wid == 0) {
        int nw = blockDim.x >> 5;
        float v = (lane < nw) ? sm[lane] : 0.f;
#pragma unroll
        for (int off = 16; off > 0; off >>= 1)
            v += __shfl_down_sync(0xffffffffu, v, off);
        if (lane == 0) r[row] = v;
    }
}

// ================= fused split-convert (+ stats/rl zeroing) =================
struct alignas(16) bf16x8 { __nv_bfloat16 v[8]; };
struct CvtSeg { const float* src; __nv_bfloat16* dh; __nv_bfloat16* dl; int K; unsigned base; };
struct CvtArgs { CvtSeg seg[7]; unsigned total; };

__global__ void convert_all_kernel(CvtArgs args, float* __restrict__ rlz) {
    unsigned gid = blockIdx.x * blockDim.x + threadIdx.x;
    if (gid < 5) g_stats[gid] = 0.0;
    if (gid < N_ROWS) rlz[gid] = 0.f;
    if (gid >= args.total) return;
    int si = 0;
#pragma unroll
    for (int i = 1; i < 7; i++)
        if (gid >= args.seg[i].base) si = i;
    const CvtSeg s = args.seg[si];
    unsigned idx = gid - s.base;
    int K = s.K, gpr = K >> 3, nkc = K >> 6;
    int r  = idx / gpr;
    int k0 = (idx - r * gpr) * 8;

    const float* p = s.src + (size_t)r * K + k0;
    float4 v0 = *(const float4*)p;
    float4 v1 = *(const float4*)(p + 4);
    float f[8] = {v0.x, v0.y, v0.z, v0.w, v1.x, v1.y, v1.z, v1.w};

    bf16x8 ph, pl;
#pragma unroll
    for (int m = 0; m < 8; m++) {
        __nv_bfloat16 h = __float2bfloat16(f[m]);
        ph.v[m] = h;
        pl.v[m] = __float2bfloat16(f[m] - __bfloat162float(h));
    }

    int rb = r >> 7, lr = r & 127;
    int kc = k0 >> 6, g = (k0 & 63) >> 3;
    int gsw = g ^ (lr & 7);
    size_t off = (((size_t)rb * nkc + kc) * 128 + lr) * 64 + gsw * 8;
    *(bf16x8*)&s.dh[off] = ph;
    *(bf16x8*)&s.dl[off] = pl;
}

// ================= tcgen05 GEMM + bias + LeakyReLU (R9 config + L2 prefetch) =====
#define GS 3
__global__ void __launch_bounds__(256, 1)
tc_gemm_bias_lrelu(const __nv_bfloat16* __restrict__ ah, const __nv_bfloat16* __restrict__ al,
                   const __nv_bfloat16* __restrict__ wh, const __nv_bfloat16* __restrict__ wl,
                   const float* __restrict__ bias,
                   float* __restrict__ Cfp,
                   __nv_bfloat16* __restrict__ oh, __nv_bfloat16* __restrict__ ol,
                   float* __restrict__ rnorm,
                   int N, int NC, int write_fp32, int write_split) {
    const int nb = blockIdx.x, mb = blockIdx.y;
    const int n0 = nb * 128, m0 = mb * 128;
    const int t = threadIdx.x;

#if HAS_TCGEN05
    extern __shared__ char dsm_raw[];
    char* dsm = (char*)(((uintptr_t)dsm_raw + 1023) & ~(uintptr_t)1023);
    __shared__ __align__(8) unsigned long long s_mbar[2 * GS + 1];
    __shared__ uint32_t s_tmem;

    const int wid = t >> 5;
    const int lid = t & 31;
    const uint32_t mb0   = smem_u32(&s_mbar[0]);
    const uint32_t donem = mb0 + 2 * GS * 8;
#define FULLB(b)  (mb0 + (uint32_t)(b) * 8)
#define EMPTYB(b) (mb0 + (uint32_t)(GS + (b)) * 8)

    if (wid == 0) TC_ALLOC(smem_u32(&s_tmem), 128);
    if (t == 0) {
        for (int k = 0; k < 2 * GS; k++) MBAR_INIT(mb0 + k * 8, 1);
        MBAR_INIT(donem, 1);
    }
    __syncthreads();
    const uint32_t D = s_tmem;
    const uint32_t smem_base = smem_u32(dsm);

    if (wid == 0 && elect_one()) {
        auto prefetch = [&](int n) {
            BULK_PREF((const char*)(ah + ((size_t)mb * NC + n) * TILE_ELEMS), TILE_BYTES);
            BULK_PREF((const char*)(al + ((size_t)mb * NC + n) * TILE_ELEMS), TILE_BYTES);
            BULK_PREF((const char*)(wh + ((size_t)nb * NC + n) * TILE_ELEMS), TILE_BYTES);
            BULK_PREF((const char*)(wl + ((size_t)nb * NC + n) * TILE_ELEMS), TILE_BYTES);
        };
        const int np = (NC < GS) ? NC : GS;
        for (int k = 0; k < np; k++) {
            const uint32_t bufb = smem_base + (uint32_t)k * 65536;
            MBAR_EXPECT_TX(FULLB(k), 65536);
            BULK_G2S(bufb,         (const char*)(ah + ((size_t)mb * NC + k) * TILE_ELEMS), TILE_BYTES, FULLB(k));
            BULK_G2S(bufb + 16384, (const char*)(al + ((size_t)mb * NC + k) * TILE_ELEMS), TILE_BYTES, FULLB(k));
            BULK_G2S(bufb + 32768, (const char*)(wh + ((size_t)nb * NC + k) * TILE_ELEMS), TILE_BYTES, FULLB(k));
            BULK_G2S(bufb + 49152, (const char*)(wl + ((size_t)nb * NC + k) * TILE_ELEMS), TILE_BYTES, FULLB(k));
            if (k + GS < NC) prefetch(k + GS);
        }
#pragma unroll 1
        for (int n = 0; n < NC; n++) {
            const int b = n % GS, q = n / GS;
            const uint32_t bufb = smem_base + (uint32_t)b * 65536;
            mbar_wait_parity(FULLB(b), (uint32_t)(q & 1));

            uint64_t dAh = make_desc(bufb);
            uint64_t dAl = make_desc(bufb + 16384);
            uint64_t dWh = make_desc(bufb + 32768);
            uint64_t dWl = make_desc(bufb + 49152);
#pragma unroll
            for (int s = 0; s < 4; s++) {
                uint64_t off = s * 2;
                mma_f16_ss(D, dAh + off, dWh + off, IDESC_N128, !(n == 0 && s == 0));
                mma_f16_ss(D, dAh + off, dWl + off, IDESC_N128, true);
                mma_f16_ss(D, dAl + off, dWh + off, IDESC_N128, true);
            }
            TC_COMMIT(EMPTYB(b));

            if (n + GS < NC) {
                const int m = n + GS;
                mbar_wait_parity(EMPTYB(b), (uint32_t)(q & 1));
                MBAR_EXPECT_TX(FULLB(b), 65536);
                BULK_G2S(bufb,         (const char*)(ah + ((size_t)mb * NC + m) * TILE_ELEMS), TILE_BYTES, FULLB(b));
                BULK_G2S(bufb + 16384, (const char*)(al + ((size_t)mb * NC + m) * TILE_ELEMS), TILE_BYTES, FULLB(b));
                BULK_G2S(bufb + 32768, (const char*)(wh + ((size_t)nb * NC + m) * TILE_ELEMS), TILE_BYTES, FULLB(b));
                BULK_G2S(bufb + 49152, (const char*)(wl + ((size_t)nb * NC + m) * TILE_ELEMS), TILE_BYTES, FULLB(b));
                if (m + GS < NC) prefetch(m + GS);
            }
        }
        for (int n = (NC > GS ? NC - GS : 0); n < NC; n++)
            mbar_wait_parity(EMPTYB(n % GS), (uint32_t)((n / GS) & 1));
        MBAR_ARRIVE(donem);
    }
    mbar_wait_parity(donem, 0u);
    TC_FENCE_AFTER();

    const int wg  = wid >> 2;
    const int sub = wid & 3;
    const int lr  = sub * 32 + lid;
    const int m   = m0 + lr;
    const int nkc_out = N >> 6;
    float ssum = 0.f;

#pragma unroll
    for (int bb = 0; bb < 2; bb++) {
        const int colbase = wg * 64 + bb * 32;
        uint32_t dr[32];
        LDTM32(dr, D + colbase);
        TC_WAIT_LD();
        float v[32];
#pragma unroll
        for (int c = 0; c < 32; c++) {
            float x = __uint_as_float(dr[c]) + __ldg(&bias[n0 + colbase + c]);
            v[c] = (x >= 0.f) ? x : SLOPE * x;
        }
        if (rnorm) {
#pragma unroll
            for (int c = 0; c < 32; c++) ssum += v[c] * v[c];
        }
        if (write_fp32) {
#pragma unroll
            for (int c = 0; c < 32; c++)
                Cfp[(size_t)m * N + n0 + colbase + c] = v[c];
        }
        if (write_split) {
#pragma unroll
            for (int g8 = 0; g8 < 4; g8++) {
                int nn = n0 + colbase + g8 * 8;
                int kc = nn >> 6, g = (nn & 63) >> 3;
                int gsw = g ^ (lr & 7);
                size_t off = (((size_t)mb * nkc_out + kc) * 128 + lr) * 64 + gsw * 8;
                bf16x8 ph, pl;
#pragma unroll
                for (int e = 0; e < 8; e++) {
                    float x = v[g8 * 8 + e];
                    __nv_bfloat16 h = __float2bfloat16(x);
                    ph.v[e] = h;
                    pl.v[e] = __float2bfloat16(x - __bfloat162float(h));
                }
                *(bf16x8*)&oh[off] = ph;
                *(bf16x8*)&ol[off] = pl;
            }
        }
    }
    if (rnorm) atomicAdd(&rnorm[m], ssum);   // 2 commutative adds/row: deterministic

    __syncthreads();
    if (t == 0) {
        for (int k = 0; k < 2 * GS; k++) MBAR_INVAL(mb0 + k * 8);
        MBAR_INVAL(donem);
    }
    __syncthreads();
    if (wid == 0) TC_DEALLOC(D, 128);
#undef FULLB
#undef EMPTYB

#else
    const int K = NC * 64;
    const int lr0 = t & 127;
    const int m = m0 + lr0;
    const int jh = (t >> 7) * 64;
    const int nkc_out = N >> 6;
    float ssum = 0.f;
    for (int jj = 0; jj < 64; jj++) {
        int nn = n0 + jh + jj;
        int wrb = nn >> 7, wlr = nn & 127;
        float acc = 0.f;
        for (int k = 0; k < K; k++) {
            int kc = k >> 6, g = (k & 63) >> 3, e = k & 7;
            size_t aoff = (((size_t)mb * NC + kc) * 128 + lr0) * 64 + (size_t)((g ^ (lr0 & 7)) * 8 + e);
            size_t woff = (((size_t)wrb * NC + kc) * 128 + wlr) * 64 + (size_t)((g ^ (wlr & 7)) * 8 + e);
            float av = __bfloat162float(ah[aoff]) + __bfloat162float(al[aoff]);
            float wv = __bfloat162float(wh[woff]) + __bfloat162float(wl[woff]);
            acc += av * wv;
        }
        float x = acc + bias[nn];
        x = (x >= 0.f) ? x : SLOPE * x;
        if (rnorm) ssum += x * x;
        if (write_fp32) Cfp[(size_t)m * N + nn] = x;
        if (write_split) {
            __nv_bfloat16 h = __float2bfloat16(x);
            int kc = nn >> 6, g = (nn & 63) >> 3;
            size_t off = (((size_t)mb * nkc_out + kc) * 128 + lr0) * 64 + (size_t)((g ^ (lr0 & 7)) * 8 + (nn & 7));
            oh[off] = h;
            ol[off] = __float2bfloat16(x - __bfloat162float(h));
        }
    }
    if (rnorm) atomicAdd(&rnorm[m], ssum);
#endif
}

// ================= fused Gram + distance + stats, 128x256 tiles, depth-4 =================
#define DS 4
__global__ void __launch_bounds__(256, 1)
dist_stats_tc_kernel(const __nv_bfloat16* __restrict__ xh,
                     const __nv_bfloat16* __restrict__ lh,
                     const float* __restrict__ rx,
                     const float* __restrict__ rl) {
    int b = blockIdx.x;
    int bi = 0, rem = b;
    while (rem >= NBJ - (bi >> 1)) { rem -= NBJ - (bi >> 1); bi++; }
    int jb2 = (bi >> 1) + rem;
    const bool dcheck = (jb2 == (bi >> 1));
    const int i0 = bi * 128, j0 = jb2 * 256;

    __shared__ double red[256];
    const int t = threadIdx.x;

    float fs1 = 0.f, fs2 = 0.f, fs11 = 0.f, fs22 = 0.f, fs12 = 0.f;

#if HAS_TCGEN05
    extern __shared__ char dsm_raw[];
    char* dsm = (char*)(((uintptr_t)dsm_raw + 1023) & ~(uintptr_t)1023);
    __shared__ __align__(8) unsigned long long s_mbar[2 * DS + 1];
    __shared__ uint32_t s_tmem;

    const int wid = t >> 5;
    const int lid = t & 31;
    const uint32_t mb0   = smem_u32(&s_mbar[0]);
    const uint32_t donem = mb0 + 2 * DS * 8;
#define FULLB(b)  (mb0 + (uint32_t)(b) * 8)
#define EMPTYB(b) (mb0 + (uint32_t)(DS + (b)) * 8)

    if (wid == 0) TC_ALLOC(smem_u32(&s_tmem), 512);
    if (t == 0) {
        for (int k = 0; k < 2 * DS; k++) MBAR_INIT(mb0 + k * 8, 1);
        MBAR_INIT(donem, 1);
    }
    __syncthreads();
    const uint32_t tmem = s_tmem;
    const uint32_t D_X = tmem, D_L = tmem + 256;
    const uint32_t smem_base = smem_u32(dsm);

    if (wid == 0 && elect_one()) {
        auto docopy = [&](int n, int bsel) {
            const __nv_bfloat16 *base; int nkc, arow;
            if (n < NKC_L) { base = lh; nkc = NKC_L; arow = n; }
            else           { base = xh; nkc = NKC_X; arow = n - NKC_L; }
            const uint32_t bufb = smem_base + (uint32_t)bsel * 49152;
            const uint32_t fb = FULLB(bsel);
            MBAR_EXPECT_TX(fb, 49152);
            BULK_G2S(bufb, (const char*)(base + ((size_t)bi * nkc + arow) * TILE_ELEMS), TILE_BYTES, fb);
            BULK_G2S(bufb + 16384, (const char*)(base + ((size_t)(jb2 * 2) * nkc + arow) * TILE_ELEMS), TILE_BYTES, fb);
            BULK_G2S(bufb + 32768, (const char*)(base + ((size_t)(jb2 * 2 + 1) * nkc + arow) * TILE_ELEMS), TILE_BYTES, fb);
        };
        for (int k = 0; k < DS; k++) docopy(k, k);

#pragma unroll 1
        for (int n = 0; n < NCH_DIST; n++) {
            const int bsel = n % DS, q = n / DS;
            const uint32_t bufb = smem_base + (uint32_t)bsel * 49152;
            mbar_wait_parity(FULLB(bsel), (uint32_t)(q & 1));

            const uint32_t Dacc = (n < NKC_L) ? D_L : D_X;
            const bool first = (n == 0) || (n == NKC_L);
            uint64_t dA = make_desc(bufb), dB = make_desc(bufb + 16384);
#pragma unroll
            for (int s = 0; s < 4; s++)
                mma_f16_ss(Dacc, dA + s * 2, dB + s * 2, IDESC_N256, !(first && s == 0));
            TC_COMMIT(EMPTYB(bsel));

            if (n + DS < NCH_DIST) {
                mbar_wait_parity(EMPTYB(bsel), (uint32_t)(q & 1));
                docopy(n + DS, bsel);
            }
        }
        for (int n = NCH_DIST - DS; n < NCH_DIST; n++)
            mbar_wait_parity(EMPTYB(n % DS), (uint32_t)((n / DS) & 1));
        MBAR_ARRIVE(donem);
    }
    mbar_wait_parity(donem, 0u);
    TC_FENCE_AFTER();

    const int wg  = wid >> 2;
    const int sub = wid & 3;
    const int i = i0 + sub * 32 + lid;
    const float rxi = __ldg(&rx[i]);
    const float rli = __ldg(&rl[i]);

#pragma unroll 1
    for (int bb = 0; bb < 4; bb++) {
        const int colbase = wg * 128 + bb * 32;
        uint32_t xg[32], lg[32];
        LDTM32(xg, D_X + colbase);
        LDTM32(lg, D_L + colbase);
        TC_WAIT_LD();
#pragma unroll
        for (int c = 0; c < 32; c++) {
            int j = j0 + colbase + c;
            if (!dcheck || j > i) {
                float gx = __uint_as_float(xg[c]);
                float gl = __uint_as_float(lg[c]);
                float sqx = rxi + __ldg(&rx[j]) - 2.f * gx;
                float sql = rli + __ldg(&rl[j]) - 2.f * gl;
                float dx = sqrtf(fmaxf(sqx, 0.f));
                float dv = sqrtf(fmaxf(sql, 0.f));
                fs1  += dx;
                fs2  += dv;
                fs11 += dx * dx;
                fs22 += dv * dv;
                fs12 += dx * dv;
            }
        }
    }

    __syncthreads();
    if (t == 0) {
        for (int k = 0; k < 2 * DS; k++) MBAR_INVAL(mb0 + k * 8);
        MBAR_INVAL(donem);
    }
    __syncthreads();
    if (wid == 0) TC_DEALLOC(tmem, 512);
#undef FULLB
#undef EMPTYB

#else  // fallback: dequant fp32 hi-only
    const int tx = (t & 15) * 16;
    const int ty = (t >> 4) * 8;
    for (int ii = 0; ii < 8; ii++) {
        int i = i0 + ty + ii;
        float rxi = rx[i], rli = rl[i];
        int ib = i >> 7, ilr = i & 127;
        for (int jj = 0; jj < 16; jj++) {
            int j = j0 + tx + jj;
            if (dcheck && j <= i) continue;
            int jb = j >> 7, jlr = j & 127;
            float gx = 0.f, gl = 0.f;
            for (int k = 0; k < DIM; k++) {
                int kc = k >> 6, g = (k & 63) >> 3, e = k & 7;
                size_t ioff = (((size_t)ib * NKC_X + kc) * 128 + ilr) * 64 + (size_t)((g ^ (ilr & 7)) * 8 + e);
                size_t joff = (((size_t)jb * NKC_X + kc) * 128 + jlr) * 64 + (size_t)((g ^ (jlr & 7)) * 8 + e);
                gx += __bfloat162float(xh[ioff]) * __bfloat162float(xh[joff]);
            }
            for (int k = 0; k < LAT; k++) {
                int kc = k >> 6, g = (k & 63) >> 3, e = k & 7;
                size_t ioff = (((size_t)ib * NKC_L + kc) * 128 + ilr) * 64 + (size_t)((g ^ (ilr & 7)) * 8 + e);
                size_t joff = (((size_t)jb * NKC_L + kc) * 128 + jlr) * 64 + (size_t)((g ^ (jlr & 7)) * 8 + e);
                gl += __bfloat162float(lh[ioff]) * __bfloat162float(lh[joff]);
            }
            float dx = sqrtf(fmaxf(rxi + rx[j] - 2.f * gx, 0.f));
            float dv = sqrtf(fmaxf(rli + rl[j] - 2.f * gl, 0.f));
            fs1 += dx; fs2 += dv; fs11 += dx * dx; fs22 += dv * dv; fs12 += dx * dv;
        }
    }
#endif

    float vals[5] = {fs1, fs2, fs11, fs22, fs12};
#pragma unroll
    for (int v = 0; v < 5; v++) {
        red[t] = (double)vals[v];
        __syncthreads();
        for (int off = 128; off > 0; off >>= 1) {
            if (t < off) red[t] += red[t + off];
            __syncthreads();
        }
        if (t == 0) atomicAdd(&g_stats[v], red[0]);
        __syncthreads();
    }
}

__global__ void finalize_kernel(float* __restrict__ out, long long idx) {
    const double n = (double)N_ROWS * (double)N_ROWS;
    double s1  = 2.0 * g_stats[0];
    double s2  = 2.0 * g_stats[1];
    double s11 = 2.0 * g_stats[2];
    double s22 = 2.0 * g_stats[3];
    double s12 = 2.0 * g_stats[4];
    double m1 = s1 / n;
    double m2 = s2 / n;
    double v1 = (s11 - n * m1 * m1) / (n - 1.0);
    double v2 = (s22 - n * m2 * m2) / (n - 1.0);
    double cov = s12 / n - m1 * m2;
    out[idx] = (float)(cov / sqrt(v1 * v2));
}

extern "C" void kernel_launch(void* const* d_in, const int* in_sizes, int n_in,
                              void* d_out, int out_size) {
    const float* x   = (const float*)d_in[0];
    const float* We1 = (const float*)d_in[1];
    const float* be1 = (const float*)d_in[2];
    const float* We2 = (const float*)d_in[3];
    const float* be2 = (const float*)d_in[4];
    const float* We3 = (const float*)d_in[5];
    const float* be3 = (const float*)d_in[6];
    const float* Wd1 = (const float*)d_in[7];
    const float* bd1 = (const float*)d_in[8];
    const float* Wd2 = (const float*)d_in[9];
    const float* bd2 = (const float*)d_in[10];
    const float* Wd3 = (const float*)d_in[11];
    const float* bd3 = (const float*)d_in[12];
    float* out = (float*)d_out;

    float* lat = nullptr; cudaGetSymbolAddress((void**)&lat, g_lat);
    float* rx  = nullptr; cudaGetSymbolAddress((void**)&rx,  g_rx);
    float* rl  = nullptr; cudaGetSymbolAddress((void**)&rl,  g_rl);
#define SYM(T, v, s) T* v = nullptr; cudaGetSymbolAddress((void**)&v, s)
    SYM(__nv_bfloat16, xh, g_xh);   SYM(__nv_bfloat16, xl, g_xl);
    SYM(__nv_bfloat16, lh, g_lh);   SYM(__nv_bfloat16, ll, g_ll);
    SYM(__nv_bfloat16, a1h, g_a1h); SYM(__nv_bfloat16, a1l, g_a1l);
    SYM(__nv_bfloat16, a2h, g_a2h); SYM(__nv_bfloat16, a2l, g_a2l);
    SYM(__nv_bfloat16, a4h, g_a4h); SYM(__nv_bfloat16, a4l, g_a4l);
    SYM(__nv_bfloat16, a5h, g_a5h); SYM(__nv_bfloat16, a5l, g_a5l);
    SYM(__nv_bfloat16, we1h, g_we1h); SYM(__nv_bfloat16, we1l, g_we1l);
    SYM(__nv_bfloat16, we2h, g_we2h); SYM(__nv_bfloat16, we2l, g_we2l);
    SYM(__nv_bfloat16, we3h, g_we3h); SYM(__nv_bfloat16, we3l, g_we3l);
    SYM(__nv_bfloat16, wd1h, g_wd1h); SYM(__nv_bfloat16, wd1l, g_wd1l);
    SYM(__nv_bfloat16, wd2h, g_wd2h); SYM(__nv_bfloat16, wd2l, g_wd2l);
    SYM(__nv_bfloat16, wd3h, g_wd3h); SYM(__nv_bfloat16, wd3l, g_wd3l);
#undef SYM

    static cudaStream_t s2 = nullptr;
    static cudaEvent_t ev_cvt = nullptr, ev_fork = nullptr, ev_join = nullptr;
    if (s2 == nullptr) {
        cudaStreamCreateWithFlags(&s2, cudaStreamNonBlocking);
        cudaEventCreateWithFlags(&ev_cvt, cudaEventDisableTiming);
        cudaEventCreateWithFlags(&ev_fork, cudaEventDisableTiming);
        cudaEventCreateWithFlags(&ev_join, cudaEventDisableTiming);
    }

    {
        CvtArgs a;
        unsigned base = 0;
        auto set = [&](int i, const float* src, __nv_bfloat16* dh, __nv_bfloat16* dl,
                       int rows, int K) {
            a.seg[i] = {src, dh, dl, K, base};
            base += (unsigned)(rows * K / 8);
        };
        set(0, x,   xh,   xl,   N_ROWS, DIM);
        set(1, We1, we1h, we1l, H1,  DIM);
        set(2, We2, we2h, we2l, H2,  H1);
        set(3, We3, we3h, we3l, LAT, H2);
        set(4, Wd1, wd1h, wd1l, H2,  LAT);
        set(5, Wd2, wd2h, wd2l, H1,  H2);
        set(6, Wd3, wd3h, wd3l, DIM, H1);
        a.total = base;
        convert_all_kernel<<<(base + 255) / 256, 256>>>(a, rl);
    }
    // rownorm(x) off the critical path: only dist consumes it
    cudaEventRecord(ev_cvt, 0);
    cudaStreamWaitEvent(s2, ev_cvt, 0);
    rownorm_kernel<<<N_ROWS, 256, 0, s2>>>(x, rx, DIM);

    const int smem_gemm = GS * 65536 + 1024;
    const int smem_dist = DS * 49152 + 1024;
    cudaFuncSetAttribute(tc_gemm_bias_lrelu, cudaFuncAttributeMaxDynamicSharedMemorySize, smem_gemm);
    cudaFuncSetAttribute(dist_stats_tc_kernel, cudaFuncAttributeMaxDynamicSharedMemorySize, smem_dist);

#define TCL(ah_, al_, wh_, wl_, b_, c_, oh_, ol_, rn_, N_, K_, wf, ws) \
    tc_gemm_bias_lrelu<<<dim3((N_) / 128, NB), 256, smem_gemm>>>( \
        ah_, al_, wh_, wl_, b_, c_, oh_, ol_, rn_, N_, (K_) / 64, wf, ws)
    // encoder; layer-3 fuses rownorm(latent) via atomicAdd into rl
    TCL(xh,  xl,  we1h, we1l, be1, (float*)nullptr, a1h, a1l, (float*)nullptr, H1,  DIM, 0, 1);
    TCL(a1h, a1l, we2h, we2l, be2, (float*)nullptr, a2h, a2l, (float*)nullptr, H2,  H1,  0, 1);
    TCL(a2h, a2l, we3h, we3l, be3, (float*)nullptr, lh,  ll,  rl,              LAT, H2,  0, 1);

    // fork: dist depends on xh, lh, rx, rl -> concurrent with decoder
    cudaEventRecord(ev_fork, 0);
    cudaStreamWaitEvent(s2, ev_fork, 0);
    {
        int nblk = 0;
        for (int bi = 0; bi < NB; bi++) nblk += NBJ - (bi >> 1);
        dist_stats_tc_kernel<<<nblk, 256, smem_dist, s2>>>(xh, lh, rx, rl);
    }
    cudaEventRecord(ev_join, s2);

    // decoder on main stream, concurrent with dist
    TCL(lh,  ll,  wd1h, wd1l, bd1, (float*)nullptr, a4h, a4l, (float*)nullptr, H2,  LAT, 0, 1);
    TCL(a4h, a4l, wd2h, wd2l, bd2, (float*)nullptr, a5h, a5l, (float*)nullptr, H1,  H2,  0, 1);
    TCL(a5h, a5l, wd3h, wd3l, bd3, out, (__nv_bfloat16*)nullptr, (__nv_bfloat16*)nullptr, (float*)nullptr, DIM, H1, 1, 0);
#undef TCL

    cudaStreamWaitEvent(0, ev_join, 0);
    finalize_kernel<<<1, 1>>>(out, (long long)out_size - 1);
}